// round 6
// baseline (speedup 1.0000x reference)
#include <cuda_runtime.h>
#include <cuda_bf16.h>
#include <math.h>
#include <stdint.h>

#define Bb   16
#define Mt   16
#define Dd   512
#define Ne   16
#define Hh   682
#define NHt  (Ne*Hh)      /* 10912 */
#define Rows (Bb*Mt)      /* 256   */
#define OUTD 512
#define YSPLIT 16
#define OSPLIT 64

typedef unsigned long long ull;
typedef __nv_bfloat16 bf16;

// ---- packed fp32 helpers ----
__device__ __forceinline__ ull pk2(float lo, float hi) {
    ull r; asm("mov.b64 %0,{%1,%2};" : "=l"(r) : "f"(lo), "f"(hi)); return r;
}
__device__ __forceinline__ void upk2(ull v, float& lo, float& hi) {
    asm("mov.b64 {%0,%1},%2;" : "=f"(lo), "=f"(hi) : "l"(v));
}
__device__ __forceinline__ ull fma2(ull a, ull b, ull c) {
    ull d; asm("fma.rn.f32x2 %0,%1,%2,%3;" : "=l"(d) : "l"(a), "l"(b), "l"(c)); return d;
}

// ---- warp mma: D(16x8 f32) += A(16x16 bf16) * B(16x8 bf16) ----
__device__ __forceinline__ void mma_bf16(float* c, uint32_t a0, uint32_t a1, uint32_t a2, uint32_t a3,
                                         uint32_t b0, uint32_t b1) {
    asm volatile("mma.sync.aligned.m16n8k16.row.col.f32.bf16.bf16.f32 "
        "{%0,%1,%2,%3}, {%4,%5,%6,%7}, {%8,%9}, {%0,%1,%2,%3};"
        : "+f"(c[0]), "+f"(c[1]), "+f"(c[2]), "+f"(c[3])
        : "r"(a0), "r"(a1), "r"(a2), "r"(a3), "r"(b0), "r"(b1));
}

__device__ __forceinline__ void split2(float v, bf16& h, bf16& l) {
    h = __float2bfloat16(v);
    l = __float2bfloat16(v - __bfloat162float(h));
}
__device__ __forceinline__ void st_split(bf16* gh, bf16* gl, long long idx, float v) {
    bf16 h, l; split2(v, h, l);
    gh[idx] = h; gl[idx] = l;
}

// ---------------- scratch ----------------
__device__ float g_logits[Rows*NHt];
__device__ float g_Dw[Rows*NHt];
__device__ float g_Cw[Rows*NHt];
__device__ float g_XW1[Rows*NHt];
__device__ float g_Ypart[YSPLIT*Rows*OUTD];
__device__ float g_Y[Rows*OUTD];
__device__ float g_b2sum[OUTD];
__device__ float g_opart[OSPLIT*Bb*OUTD];
// bf16 hi/lo A-side buffers (reused operands only)
__device__ bf16 g_xh[Rows*Dd],  g_xl[Rows*Dd];
__device__ bf16 g_gh[Rows*NHt], g_gl[Rows*NHt];

// ---------------- fp32 -> bf16 hi/lo split (float4 per thread) ----------------
__global__ void cvt_split(const float* __restrict__ src, bf16* __restrict__ hi,
                          bf16* __restrict__ lo, int n4)
{
    const int i = blockIdx.x * blockDim.x + threadIdx.x;
    if (i >= n4) return;
    const float4 v = ((const float4*)src)[i];
    bf16 h[4], l[4];
    const float vv[4] = {v.x, v.y, v.z, v.w};
    #pragma unroll
    for (int e = 0; e < 4; ++e) split2(vv[e], h[e], l[e]);
    *(ull*)(hi + i * 4) = *(const ull*)h;
    *(ull*)(lo + i * 4) = *(const ull*)l;
}

// ---------------- mma.sync bf16-split GEMM, B converted in-loader ----------------
// C(+split-K partials) [z][256][Nc] = A[256][K] @ B[K][Nc]
// A: pre-split bf16 hi/lo.  B: fp32, converted to hi/lo while staging.
// MODE 0: B row-major [K, Nc].  MODE 1: B[k][j] = W1[n][k][h], j=n*Hh+h (W1 [N,K,Hh]).
// block tile 64(m) x 128(n); 8 warps (2m x 4n); warp tile 32x32; K-chunks of 64.
#define AS_STR 72   /* bf16 units */
#define BS_STR 74   /* bf16 units */
#define SM_AH 0
#define SM_AL (SM_AH + 64*AS_STR*2)
#define SM_BH (SM_AL + 64*AS_STR*2)
#define SM_BL (SM_BH + 128*BS_STR*2)
#define MG_SMEM (SM_BL + 128*BS_STR*2)       /* 56320 */

template<int MODE>
__global__ __launch_bounds__(256) void mma_gemm(
    const bf16* __restrict__ Ah, const bf16* __restrict__ Al,
    const float* __restrict__ Bm,
    float* __restrict__ C, int Nc, int K, int nsplit)
{
    extern __shared__ __align__(16) char sm[];
    bf16* sAh = (bf16*)(sm + SM_AH);
    bf16* sAl = (bf16*)(sm + SM_AL);
    bf16* sBh = (bf16*)(sm + SM_BH);
    bf16* sBl = (bf16*)(sm + SM_BL);

    const int t = threadIdx.x;
    const int lane = t & 31, warp = t >> 5;
    const int wm = (warp & 1) * 32;
    const int wn = (warp >> 1) * 32;
    const int m0 = blockIdx.y * 64;
    const int j0 = blockIdx.x * 128;
    const int z  = blockIdx.z;
    const int nch = (K + 63) >> 6;
    const int c0 = (int)((long long)nch * z / nsplit);
    const int c1 = (int)((long long)nch * (z + 1) / nsplit);

    float acc[2][4][4];
    #pragma unroll
    for (int i = 0; i < 2; ++i)
        #pragma unroll
        for (int j = 0; j < 4; ++j)
            #pragma unroll
            for (int e = 0; e < 4; ++e) acc[i][j][e] = 0.f;

    const int gid = lane >> 2;
    const int qid = lane & 3;

    // B loader per-slot (n,h) precompute for MODE 1
    int bn[8], bh[8];
    if (MODE == 1) {
        #pragma unroll
        for (int it = 0; it < 8; ++it) {
            const int g = (t + it * 256) & 31;
            const int j = j0 + g * 4;
            int n = j / Hh;
            bn[it] = n;
            bh[it] = j - n * Hh;
        }
    }

    for (int c = c0; c < c1; ++c) {
        const int k0 = c << 6;
        __syncthreads();
        // ---- A tiles (pre-split bf16): 64 rows x 64 k
        #pragma unroll
        for (int it = 0; it < 4; ++it) {
            const int s = t + it * 256;
            const int kq = s & 15;
            const int row = s >> 4;
            const int gk = k0 + kq * 4;
            const long long ga = (long long)(m0 + row) * K + gk;
            ull vh = 0, vl = 0;
            if (gk + 4 <= K) { vh = *(const ull*)(Ah + ga); vl = *(const ull*)(Al + ga); }
            *(ull*)(sAh + row * AS_STR + kq * 4) = vh;
            *(ull*)(sAl + row * AS_STR + kq * 4) = vl;
        }
        // ---- B tiles: fp32 -> bf16 hi/lo, transposed to [n][k]
        #pragma unroll
        for (int it = 0; it < 8; ++it) {
            const int s = t + it * 256;
            const int g = s & 31;
            const int k = s >> 5;
            const int gj = j0 + g * 4;
            const int gk = k0 + k;
            float vv[4] = {0.f, 0.f, 0.f, 0.f};
            if (MODE == 0) {
                if (gj + 4 <= Nc && gk < K) {
                    const float4 v = *(const float4*)(Bm + (long long)gk * Nc + gj);
                    vv[0] = v.x; vv[1] = v.y; vv[2] = v.z; vv[3] = v.w;
                }
            } else {
                if (gk < K) {
                    int n = bn[it], h = bh[it];
                    #pragma unroll
                    for (int e = 0; e < 4; ++e) {
                        if (gj + e < Nc) vv[e] = Bm[((long long)n * K + gk) * Hh + h];
                        if (++h >= Hh) { h = 0; ++n; }
                    }
                }
            }
            #pragma unroll
            for (int e = 0; e < 4; ++e) {
                bf16 h, l; split2(vv[e], h, l);
                sBh[(g * 4 + e) * BS_STR + k] = h;
                sBl[(g * 4 + e) * BS_STR + k] = l;
            }
        }
        __syncthreads();

        #pragma unroll
        for (int ks = 0; ks < 4; ++ks) {
            const int kcol = ks * 16 + qid * 2;
            uint32_t ah[2][4], al[2][4];
            #pragma unroll
            for (int mi = 0; mi < 2; ++mi) {
                const int r = wm + mi * 16 + gid;
                ah[mi][0] = *(const uint32_t*)(sAh + r * AS_STR + kcol);
                ah[mi][1] = *(const uint32_t*)(sAh + (r + 8) * AS_STR + kcol);
                ah[mi][2] = *(const uint32_t*)(sAh + r * AS_STR + kcol + 8);
                ah[mi][3] = *(const uint32_t*)(sAh + (r + 8) * AS_STR + kcol + 8);
                al[mi][0] = *(const uint32_t*)(sAl + r * AS_STR + kcol);
                al[mi][1] = *(const uint32_t*)(sAl + (r + 8) * AS_STR + kcol);
                al[mi][2] = *(const uint32_t*)(sAl + r * AS_STR + kcol + 8);
                al[mi][3] = *(const uint32_t*)(sAl + (r + 8) * AS_STR + kcol + 8);
            }
            uint32_t bhf[4][2], blf[4][2];
            #pragma unroll
            for (int ni = 0; ni < 4; ++ni) {
                const int n = wn + ni * 8 + gid;
                bhf[ni][0] = *(const uint32_t*)(sBh + n * BS_STR + kcol);
                bhf[ni][1] = *(const uint32_t*)(sBh + n * BS_STR + kcol + 8);
                blf[ni][0] = *(const uint32_t*)(sBl + n * BS_STR + kcol);
                blf[ni][1] = *(const uint32_t*)(sBl + n * BS_STR + kcol + 8);
            }
            #pragma unroll
            for (int mi = 0; mi < 2; ++mi)
                #pragma unroll
                for (int ni = 0; ni < 4; ++ni) {
                    mma_bf16(acc[mi][ni], ah[mi][0], ah[mi][1], ah[mi][2], ah[mi][3],
                             bhf[ni][0], bhf[ni][1]);
                    mma_bf16(acc[mi][ni], ah[mi][0], ah[mi][1], ah[mi][2], ah[mi][3],
                             blf[ni][0], blf[ni][1]);
                    mma_bf16(acc[mi][ni], al[mi][0], al[mi][1], al[mi][2], al[mi][3],
                             bhf[ni][0], bhf[ni][1]);
                }
        }
    }

    float* Cz = C + (long long)z * Rows * Nc;
    #pragma unroll
    for (int mi = 0; mi < 2; ++mi) {
        const int r0 = m0 + wm + mi * 16 + gid;
        #pragma unroll
        for (int ni = 0; ni < 4; ++ni) {
            const int cn = j0 + wn + ni * 8 + qid * 2;
            if (cn < Nc) {
                float2 lo2 = make_float2(acc[mi][ni][0], acc[mi][ni][1]);
                float2 hi2 = make_float2(acc[mi][ni][2], acc[mi][ni][3]);
                *(float2*)(Cz + (long long)r0 * Nc + cn)       = lo2;
                *(float2*)(Cz + (long long)(r0 + 8) * Nc + cn) = hi2;
            }
        }
    }
}

// ---------------- Dw = softmax over m (axis=1), float4 over columns ----------------
__global__ void softmax_m(const float* __restrict__ L, float* __restrict__ Dw)
{
    const int idx = blockIdx.x * blockDim.x + threadIdx.x;
    if (idx >= Bb * (NHt / 4)) return;
    const int b = idx / (NHt / 4);
    const int c = (idx - b * (NHt / 4)) * 4;
    const float* base = L + b * Mt * NHt + c;

    float4 v[Mt];
    float4 mx = make_float4(-3.4e38f, -3.4e38f, -3.4e38f, -3.4e38f);
    #pragma unroll
    for (int m = 0; m < Mt; ++m) {
        v[m] = *(const float4*)(base + m * NHt);
        mx.x = fmaxf(mx.x, v[m].x); mx.y = fmaxf(mx.y, v[m].y);
        mx.z = fmaxf(mx.z, v[m].z); mx.w = fmaxf(mx.w, v[m].w);
    }
    float4 s = make_float4(0.f, 0.f, 0.f, 0.f);
    #pragma unroll
    for (int m = 0; m < Mt; ++m) {
        v[m].x = expf(v[m].x - mx.x); s.x += v[m].x;
        v[m].y = expf(v[m].y - mx.y); s.y += v[m].y;
        v[m].z = expf(v[m].z - mx.z); s.z += v[m].z;
        v[m].w = expf(v[m].w - mx.w); s.w += v[m].w;
    }
    const float4 inv = make_float4(1.f/s.x, 1.f/s.y, 1.f/s.z, 1.f/s.w);
    float* ob = Dw + b * Mt * NHt + c;
    #pragma unroll
    for (int m = 0; m < Mt; ++m) {
        float4 o = make_float4(v[m].x*inv.x, v[m].y*inv.y, v[m].z*inv.z, v[m].w*inv.w);
        *(float4*)(ob + m * NHt) = o;
    }
}

// ---------------- Cw = softmax_p( softmax_n(logits) ) ----------------
__global__ void softmax_np(const float* __restrict__ L, float* __restrict__ Cw)
{
    __shared__ float s[Ne * 688];
    const int bm  = blockIdx.x;
    const int tid = threadIdx.x;
    const float* Lrow = L + bm * NHt;

    for (int idx = tid; idx < NHt; idx += 256) {
        const int n = idx / Hh, p = idx - n * Hh;
        s[n * 688 + p] = Lrow[idx];
    }
    __syncthreads();

    for (int p = tid; p < Hh; p += 256) {
        float mx = -3.4e38f;
        #pragma unroll
        for (int n = 0; n < Ne; ++n) mx = fmaxf(mx, s[n * 688 + p]);
        float sum = 0.f;
        #pragma unroll
        for (int n = 0; n < Ne; ++n) {
            const float e = expf(s[n * 688 + p] - mx);
            s[n * 688 + p] = e;
            sum += e;
        }
        const float inv = 1.f / sum;
        #pragma unroll
        for (int n = 0; n < Ne; ++n) s[n * 688 + p] *= inv;
    }
    __syncthreads();

    const int warp = tid >> 5, lane = tid & 31;
    for (int n = warp; n < Ne; n += 8) {
        float mx = -3.4e38f;
        for (int p = lane; p < Hh; p += 32) mx = fmaxf(mx, s[n * 688 + p]);
        #pragma unroll
        for (int o = 16; o; o >>= 1) mx = fmaxf(mx, __shfl_xor_sync(0xffffffffu, mx, o));
        float sum = 0.f;
        for (int p = lane; p < Hh; p += 32) {
            const float e = expf(s[n * 688 + p] - mx);
            s[n * 688 + p] = e;
            sum += e;
        }
        #pragma unroll
        for (int o = 16; o; o >>= 1) sum += __shfl_xor_sync(0xffffffffu, sum, o);
        const float inv = 1.f / sum;
        for (int p = lane; p < Hh; p += 32)
            Cw[bm * NHt + n * Hh + p] = s[n * 688 + p] * inv;
    }
}

// ---------------- b2sum ----------------
__global__ void b2sum_k(const float* __restrict__ b2, float* __restrict__ b2s)
{
    const int d = blockIdx.x * blockDim.x + threadIdx.x;
    if (d < OUTD) {
        float s = 0.f;
        #pragma unroll
        for (int n = 0; n < Ne; ++n) s += b2[n * OUTD + d];
        b2s[d] = s;
    }
}

// ---------------- fused mix -> relu -> combine (f32x2) -> bf16 hi/lo G ----------------
__global__ __launch_bounds__(256, 2) void fused_G(const float* __restrict__ XW1,
                                                  const float* __restrict__ Dw,
                                                  const float* __restrict__ Cwp,
                                                  const float* __restrict__ b1,
                                                  bf16* __restrict__ gh,
                                                  bf16* __restrict__ gl)
{
    constexpr int PC = 128;
    __shared__ __align__(16) float ds[PC][18];
    __shared__ __align__(16) float cs[PC][18];

    const int bx = blockIdx.x;
    const int n  = bx & (Ne - 1);
    const int b  = bx >> 4;
    const int tid = threadIdx.x;

    const int h0 = tid, h1 = tid + 256, h2 = tid + 512;
    const bool v3 = (h2 < Hh);

    ull xw0p[8], xw1p[8], xw2p[8];
    #pragma unroll
    for (int mp = 0; mp < 8; ++mp) {
        const int be = ((b * Mt + 2*mp    ) * Ne + n) * Hh;
        const int bo = ((b * Mt + 2*mp + 1) * Ne + n) * Hh;
        xw0p[mp] = pk2(XW1[be + h0], XW1[bo + h0]);
        xw1p[mp] = pk2(XW1[be + h1], XW1[bo + h1]);
        xw2p[mp] = v3 ? pk2(XW1[be + h2], XW1[bo + h2]) : 0ULL;
    }
    const float bb0 = b1[n * Hh + h0];
    const float bb1 = b1[n * Hh + h1];
    const float bb2 = v3 ? b1[n * Hh + h2] : 0.f;

    ull acc0[8] = {}, acc1[8] = {}, acc2[8] = {};

    for (int p0 = 0; p0 < Hh; p0 += PC) {
        const int pc = min(PC, Hh - p0);
        __syncthreads();
        for (int idx = tid; idx < Mt * PC; idx += 256) {
            const int pp = idx & (PC - 1);
            const int m  = idx >> 7;
            if (pp < pc) {
                const int a = ((b * Mt + m) * Ne + n) * Hh + p0 + pp;
                ds[pp][m] = Dw[a];
                cs[pp][m] = Cwp[a];
            }
        }
        __syncthreads();
        for (int pp = 0; pp < pc; ++pp) {
            ull r0 = 0ULL, r1 = 0ULL, r2 = 0ULL;
            #pragma unroll
            for (int mp = 0; mp < 8; ++mp) {
                const ull dp = *(const ull*)&ds[pp][2*mp];
                r0 = fma2(dp, xw0p[mp], r0);
                r1 = fma2(dp, xw1p[mp], r1);
                r2 = fma2(dp, xw2p[mp], r2);
            }
            float lo, hi, s0, s1, s2;
            upk2(r0, lo, hi); s0 = fmaxf(lo + hi + bb0, 0.f);
            upk2(r1, lo, hi); s1 = fmaxf(lo + hi + bb1, 0.f);
            upk2(r2, lo, hi); s2 = fmaxf(lo + hi + bb2, 0.f);
            const ull s0d = pk2(s0, s0);
            const ull s1d = pk2(s1, s1);
            const ull s2d = pk2(s2, s2);
            #pragma unroll
            for (int mp = 0; mp < 8; ++mp) {
                const ull cp = *(const ull*)&cs[pp][2*mp];
                acc0[mp] = fma2(cp, s0d, acc0[mp]);
                acc1[mp] = fma2(cp, s1d, acc1[mp]);
                acc2[mp] = fma2(cp, s2d, acc2[mp]);
            }
        }
    }

    #pragma unroll
    for (int mp = 0; mp < 8; ++mp) {
        const int be = ((b * Mt + 2*mp    ) * Ne + n) * Hh;
        const int bo = ((b * Mt + 2*mp + 1) * Ne + n) * Hh;
        float lo, hi;
        upk2(acc0[mp], lo, hi); st_split(gh, gl, be + h0, lo); st_split(gh, gl, bo + h0, hi);
        upk2(acc1[mp], lo, hi); st_split(gh, gl, be + h1, lo); st_split(gh, gl, bo + h1, hi);
        if (v3) { upk2(acc2[mp], lo, hi); st_split(gh, gl, be + h2, lo); st_split(gh, gl, bo + h2, hi); }
    }
}

// ---------------- reduce split-K partials for Y (float4) ----------------
__global__ void ypart_reduce(const float* __restrict__ part, const float* __restrict__ b2s,
                             float* __restrict__ Y)
{
    const int i4 = blockIdx.x * blockDim.x + threadIdx.x;
    const int idx = i4 * 4;
    const int col = idx & (OUTD - 1);
    float4 s = *(const float4*)(b2s + col);
    #pragma unroll
    for (int z = 0; z < YSPLIT; ++z) {
        float4 p = *(const float4*)(part + z * (Rows * OUTD) + idx);
        s.x += p.x; s.y += p.y; s.z += p.z; s.w += p.w;
    }
    *(float4*)(Y + idx) = s;
}

// ---------------- output GEMM ----------------
__global__ __launch_bounds__(128) void out_partial(const float* __restrict__ Y,
                                                   const float* __restrict__ Wout,
                                                   float* __restrict__ part)
{
    constexpr int KC = (Mt * Dd) / OSPLIT;   // 128
    __shared__ float ys[Bb][KC];
    const int tid = threadIdx.x;
    const int col = tid * 4;
    const int k0  = blockIdx.y * KC;

    for (int idx = tid; idx < Bb * KC; idx += 128) {
        const int bi = idx / KC, kk = idx - bi * KC;
        ys[bi][kk] = Y[bi * (Mt * Dd) + k0 + kk];
    }
    __syncthreads();

    float4 acc[Bb];
    #pragma unroll
    for (int bi = 0; bi < Bb; ++bi) acc[bi] = make_float4(0.f,0.f,0.f,0.f);

    for (int kk = 0; kk < KC; ++kk) {
        const float4 w = *(const float4*)(Wout + (k0 + kk) * OUTD + col);
        #pragma unroll
        for (int bi = 0; bi < Bb; ++bi) {
            const float yv = ys[bi][kk];
            acc[bi].x = fmaf(yv, w.x, acc[bi].x);
            acc[bi].y = fmaf(yv, w.y, acc[bi].y);
            acc[bi].z = fmaf(yv, w.z, acc[bi].z);
            acc[bi].w = fmaf(yv, w.w, acc[bi].w);
        }
    }
    #pragma unroll
    for (int bi = 0; bi < Bb; ++bi)
        *(float4*)(part + (blockIdx.y * Bb + bi) * OUTD + col) = acc[bi];
}

__global__ void out_reduce(const float* __restrict__ part, const float* __restrict__ bout,
                           float* __restrict__ out)
{
    const int i4 = blockIdx.x * blockDim.x + threadIdx.x;
    const int idx = i4 * 4;
    const int col = idx & (OUTD - 1);
    const int bi  = idx >> 9;
    float4 s = *(const float4*)(bout + col);
    #pragma unroll
    for (int z = 0; z < OSPLIT; ++z) {
        float4 p = *(const float4*)(part + (z * Bb + bi) * OUTD + col);
        s.x += p.x; s.y += p.y; s.z += p.z; s.w += p.w;
    }
    *(float4*)(out + idx) = s;
}

// ---------------- launch ----------------
extern "C" void kernel_launch(void* const* d_in, const int* in_sizes, int n_in,
                              void* d_out, int out_size)
{
    const float* x    = (const float*)d_in[0];
    const float* phi  = (const float*)d_in[1];
    const float* W1   = (const float*)d_in[2];
    const float* b1   = (const float*)d_in[3];
    const float* W2   = (const float*)d_in[4];
    const float* b2   = (const float*)d_in[5];
    const float* Wout = (const float*)d_in[6];
    const float* bout = (const float*)d_in[7];
    float* out = (float*)d_out;

    float *p_logits, *p_Dw, *p_Cw, *p_XW1, *p_Ypart, *p_Y, *p_b2sum, *p_opart;
    bf16 *p_xh, *p_xl, *p_gh, *p_gl;
    cudaGetSymbolAddress((void**)&p_logits, g_logits);
    cudaGetSymbolAddress((void**)&p_Dw,     g_Dw);
    cudaGetSymbolAddress((void**)&p_Cw,     g_Cw);
    cudaGetSymbolAddress((void**)&p_XW1,    g_XW1);
    cudaGetSymbolAddress((void**)&p_Ypart,  g_Ypart);
    cudaGetSymbolAddress((void**)&p_Y,      g_Y);
    cudaGetSymbolAddress((void**)&p_b2sum,  g_b2sum);
    cudaGetSymbolAddress((void**)&p_opart,  g_opart);
    cudaGetSymbolAddress((void**)&p_xh,   g_xh);
    cudaGetSymbolAddress((void**)&p_xl,   g_xl);
    cudaGetSymbolAddress((void**)&p_gh,   g_gh);
    cudaGetSymbolAddress((void**)&p_gl,   g_gl);

    cudaFuncSetAttribute(mma_gemm<0>, cudaFuncAttributeMaxDynamicSharedMemorySize, MG_SMEM);
    cudaFuncSetAttribute(mma_gemm<1>, cudaFuncAttributeMaxDynamicSharedMemorySize, MG_SMEM);

    // only x needs pre-splitting (reused across 86 column-blocks)
    cvt_split<<<(Rows*Dd/4 + 255)/256, 256>>>(x, p_xh, p_xl, Rows*Dd/4);

    const dim3 gBig((NHt + 127)/128, Rows/64, 1);            // 86 x 4
    mma_gemm<0><<<gBig, 256, MG_SMEM>>>(p_xh, p_xl, phi, p_logits, NHt, Dd, 1);
    mma_gemm<1><<<gBig, 256, MG_SMEM>>>(p_xh, p_xl, W1,  p_XW1,    NHt, Dd, 1);

    softmax_m <<<(Bb*(NHt/4) + 255)/256, 256>>>(p_logits, p_Dw);
    softmax_np<<<Rows, 256>>>(p_logits, p_Cw);
    b2sum_k   <<<(OUTD + 255)/256, 256>>>(b2, p_b2sum);

    fused_G<<<Bb*Ne, 256>>>(p_XW1, p_Dw, p_Cw, b1, p_gh, p_gl);

    const dim3 gY(OUTD/128, Rows/64, YSPLIT);                // 4 x 4 x 16
    mma_gemm<0><<<gY, 256, MG_SMEM>>>(p_gh, p_gl, W2, p_Ypart, OUTD, NHt, YSPLIT);
    ypart_reduce<<<(Rows*OUTD/4)/256, 256>>>(p_Ypart, p_b2sum, p_Y);

    const dim3 gO(1, OSPLIT, 1);
    out_partial<<<gO, 128>>>(p_Y, Wout, p_opart);
    out_reduce <<<(Bb*OUTD/4)/256, 256>>>(p_opart, bout, out);
}

// round 7
// speedup vs baseline: 1.0491x; 1.0491x over previous
#include <cuda_runtime.h>
#include <cuda_bf16.h>
#include <math.h>
#include <stdint.h>

#define Bb   16
#define Mt   16
#define Dd   512
#define Ne   16
#define Hh   682
#define NHt  (Ne*Hh)      /* 10912 */
#define Rows (Bb*Mt)      /* 256   */
#define OUTD 512
#define YSPLIT 16
#define OSPLIT 64

typedef unsigned long long ull;
typedef __nv_bfloat16 bf16;

// ---- warp mma: D(16x8 f32) += A(16x16 bf16) * B(16x8 bf16) ----
__device__ __forceinline__ void mma_bf16(float* c, uint32_t a0, uint32_t a1, uint32_t a2, uint32_t a3,
                                         uint32_t b0, uint32_t b1) {
    asm volatile("mma.sync.aligned.m16n8k16.row.col.f32.bf16.bf16.f32 "
        "{%0,%1,%2,%3}, {%4,%5,%6,%7}, {%8,%9}, {%0,%1,%2,%3};"
        : "+f"(c[0]), "+f"(c[1]), "+f"(c[2]), "+f"(c[3])
        : "r"(a0), "r"(a1), "r"(a2), "r"(a3), "r"(b0), "r"(b1));
}

__device__ __forceinline__ void split2(float v, bf16& h, bf16& l) {
    h = __float2bfloat16(v);
    l = __float2bfloat16(v - __bfloat162float(h));
}
__device__ __forceinline__ void st_split(bf16* gh, bf16* gl, long long idx, float v) {
    bf16 h, l; split2(v, h, l);
    gh[idx] = h; gl[idx] = l;
}
// pack two floats' hi/lo bf16 halves into bf16x2 regs
__device__ __forceinline__ void pksp(float x, float y, uint32_t& hr, uint32_t& lr) {
    bf16 hx, lx, hy, ly;
    split2(x, hx, lx); split2(y, hy, ly);
    __nv_bfloat162 H; H.x = hx; H.y = hy;
    __nv_bfloat162 L; L.x = lx; L.y = ly;
    hr = *(uint32_t*)&H; lr = *(uint32_t*)&L;
}

// ---------------- scratch ----------------
__device__ float g_logits[Rows*NHt];
__device__ float g_Dw[Rows*NHt];
__device__ float g_Cw[Rows*NHt];
__device__ float g_XW1[Rows*NHt];
__device__ float g_Ypart[YSPLIT*Rows*OUTD];
__device__ float g_Y[Rows*OUTD];
__device__ float g_b2sum[OUTD];
__device__ float g_opart[OSPLIT*Bb*OUTD];
__device__ bf16 g_xh[Rows*Dd],  g_xl[Rows*Dd];
__device__ bf16 g_gh[Rows*NHt], g_gl[Rows*NHt];

// ---------------- fp32 -> bf16 hi/lo split ----------------
__global__ void cvt_split(const float* __restrict__ src, bf16* __restrict__ hi,
                          bf16* __restrict__ lo, int n4)
{
    const int i = blockIdx.x * blockDim.x + threadIdx.x;
    if (i >= n4) return;
    const float4 v = ((const float4*)src)[i];
    bf16 h[4], l[4];
    const float vv[4] = {v.x, v.y, v.z, v.w};
    #pragma unroll
    for (int e = 0; e < 4; ++e) split2(vv[e], h[e], l[e]);
    *(ull*)(hi + i * 4) = *(const ull*)h;
    *(ull*)(lo + i * 4) = *(const ull*)l;
}

// ---------------- mma.sync bf16-split GEMM (as R6) ----------------
#define AS_STR 72
#define BS_STR 74
#define SM_AH 0
#define SM_AL (SM_AH + 64*AS_STR*2)
#define SM_BH (SM_AL + 64*AS_STR*2)
#define SM_BL (SM_BH + 128*BS_STR*2)
#define MG_SMEM (SM_BL + 128*BS_STR*2)

template<int MODE>
__global__ __launch_bounds__(256) void mma_gemm(
    const bf16* __restrict__ Ah, const bf16* __restrict__ Al,
    const float* __restrict__ Bm,
    float* __restrict__ C, int Nc, int K, int nsplit)
{
    extern __shared__ __align__(16) char sm[];
    bf16* sAh = (bf16*)(sm + SM_AH);
    bf16* sAl = (bf16*)(sm + SM_AL);
    bf16* sBh = (bf16*)(sm + SM_BH);
    bf16* sBl = (bf16*)(sm + SM_BL);

    const int t = threadIdx.x;
    const int lane = t & 31, warp = t >> 5;
    const int wm = (warp & 1) * 32;
    const int wn = (warp >> 1) * 32;
    const int m0 = blockIdx.y * 64;
    const int j0 = blockIdx.x * 128;
    const int z  = blockIdx.z;
    const int nch = (K + 63) >> 6;
    const int c0 = (int)((long long)nch * z / nsplit);
    const int c1 = (int)((long long)nch * (z + 1) / nsplit);

    float acc[2][4][4];
    #pragma unroll
    for (int i = 0; i < 2; ++i)
        #pragma unroll
        for (int j = 0; j < 4; ++j)
            #pragma unroll
            for (int e = 0; e < 4; ++e) acc[i][j][e] = 0.f;

    const int gid = lane >> 2;
    const int qid = lane & 3;

    int bn[8], bh[8];
    if (MODE == 1) {
        #pragma unroll
        for (int it = 0; it < 8; ++it) {
            const int g = (t + it * 256) & 31;
            const int j = j0 + g * 4;
            int n = j / Hh;
            bn[it] = n;
            bh[it] = j - n * Hh;
        }
    }

    for (int c = c0; c < c1; ++c) {
        const int k0 = c << 6;
        __syncthreads();
        #pragma unroll
        for (int it = 0; it < 4; ++it) {
            const int s = t + it * 256;
            const int kq = s & 15;
            const int row = s >> 4;
            const int gk = k0 + kq * 4;
            const long long ga = (long long)(m0 + row) * K + gk;
            ull vh = 0, vl = 0;
            if (gk + 4 <= K) { vh = *(const ull*)(Ah + ga); vl = *(const ull*)(Al + ga); }
            *(ull*)(sAh + row * AS_STR + kq * 4) = vh;
            *(ull*)(sAl + row * AS_STR + kq * 4) = vl;
        }
        #pragma unroll
        for (int it = 0; it < 8; ++it) {
            const int s = t + it * 256;
            const int g = s & 31;
            const int k = s >> 5;
            const int gj = j0 + g * 4;
            const int gk = k0 + k;
            float vv[4] = {0.f, 0.f, 0.f, 0.f};
            if (MODE == 0) {
                if (gj + 4 <= Nc && gk < K) {
                    const float4 v = *(const float4*)(Bm + (long long)gk * Nc + gj);
                    vv[0] = v.x; vv[1] = v.y; vv[2] = v.z; vv[3] = v.w;
                }
            } else {
                if (gk < K) {
                    int n = bn[it], h = bh[it];
                    #pragma unroll
                    for (int e = 0; e < 4; ++e) {
                        if (gj + e < Nc) vv[e] = Bm[((long long)n * K + gk) * Hh + h];
                        if (++h >= Hh) { h = 0; ++n; }
                    }
                }
            }
            #pragma unroll
            for (int e = 0; e < 4; ++e) {
                bf16 h, l; split2(vv[e], h, l);
                sBh[(g * 4 + e) * BS_STR + k] = h;
                sBl[(g * 4 + e) * BS_STR + k] = l;
            }
        }
        __syncthreads();

        #pragma unroll
        for (int ks = 0; ks < 4; ++ks) {
            const int kcol = ks * 16 + qid * 2;
            uint32_t ah[2][4], al[2][4];
            #pragma unroll
            for (int mi = 0; mi < 2; ++mi) {
                const int r = wm + mi * 16 + gid;
                ah[mi][0] = *(const uint32_t*)(sAh + r * AS_STR + kcol);
                ah[mi][1] = *(const uint32_t*)(sAh + (r + 8) * AS_STR + kcol);
                ah[mi][2] = *(const uint32_t*)(sAh + r * AS_STR + kcol + 8);
                ah[mi][3] = *(const uint32_t*)(sAh + (r + 8) * AS_STR + kcol + 8);
                al[mi][0] = *(const uint32_t*)(sAl + r * AS_STR + kcol);
                al[mi][1] = *(const uint32_t*)(sAl + (r + 8) * AS_STR + kcol);
                al[mi][2] = *(const uint32_t*)(sAl + r * AS_STR + kcol + 8);
                al[mi][3] = *(const uint32_t*)(sAl + (r + 8) * AS_STR + kcol + 8);
            }
            uint32_t bhf[4][2], blf[4][2];
            #pragma unroll
            for (int ni = 0; ni < 4; ++ni) {
                const int n = wn + ni * 8 + gid;
                bhf[ni][0] = *(const uint32_t*)(sBh + n * BS_STR + kcol);
                bhf[ni][1] = *(const uint32_t*)(sBh + n * BS_STR + kcol + 8);
                blf[ni][0] = *(const uint32_t*)(sBl + n * BS_STR + kcol);
                blf[ni][1] = *(const uint32_t*)(sBl + n * BS_STR + kcol + 8);
            }
            #pragma unroll
            for (int mi = 0; mi < 2; ++mi)
                #pragma unroll
                for (int ni = 0; ni < 4; ++ni) {
                    mma_bf16(acc[mi][ni], ah[mi][0], ah[mi][1], ah[mi][2], ah[mi][3],
                             bhf[ni][0], bhf[ni][1]);
                    mma_bf16(acc[mi][ni], ah[mi][0], ah[mi][1], ah[mi][2], ah[mi][3],
                             blf[ni][0], blf[ni][1]);
                    mma_bf16(acc[mi][ni], al[mi][0], al[mi][1], al[mi][2], al[mi][3],
                             bhf[ni][0], bhf[ni][1]);
                }
        }
    }

    float* Cz = C + (long long)z * Rows * Nc;
    #pragma unroll
    for (int mi = 0; mi < 2; ++mi) {
        const int r0 = m0 + wm + mi * 16 + gid;
        #pragma unroll
        for (int ni = 0; ni < 4; ++ni) {
            const int cn = j0 + wn + ni * 8 + qid * 2;
            if (cn < Nc) {
                float2 lo2 = make_float2(acc[mi][ni][0], acc[mi][ni][1]);
                float2 hi2 = make_float2(acc[mi][ni][2], acc[mi][ni][3]);
                *(float2*)(Cz + (long long)r0 * Nc + cn)       = lo2;
                *(float2*)(Cz + (long long)(r0 + 8) * Nc + cn) = hi2;
            }
        }
    }
}

// ---------------- softmax_m ----------------
__global__ void softmax_m(const float* __restrict__ L, float* __restrict__ Dw)
{
    const int idx = blockIdx.x * blockDim.x + threadIdx.x;
    if (idx >= Bb * (NHt / 4)) return;
    const int b = idx / (NHt / 4);
    const int c = (idx - b * (NHt / 4)) * 4;
    const float* base = L + b * Mt * NHt + c;

    float4 v[Mt];
    float4 mx = make_float4(-3.4e38f, -3.4e38f, -3.4e38f, -3.4e38f);
    #pragma unroll
    for (int m = 0; m < Mt; ++m) {
        v[m] = *(const float4*)(base + m * NHt);
        mx.x = fmaxf(mx.x, v[m].x); mx.y = fmaxf(mx.y, v[m].y);
        mx.z = fmaxf(mx.z, v[m].z); mx.w = fmaxf(mx.w, v[m].w);
    }
    float4 s = make_float4(0.f, 0.f, 0.f, 0.f);
    #pragma unroll
    for (int m = 0; m < Mt; ++m) {
        v[m].x = expf(v[m].x - mx.x); s.x += v[m].x;
        v[m].y = expf(v[m].y - mx.y); s.y += v[m].y;
        v[m].z = expf(v[m].z - mx.z); s.z += v[m].z;
        v[m].w = expf(v[m].w - mx.w); s.w += v[m].w;
    }
    const float4 inv = make_float4(1.f/s.x, 1.f/s.y, 1.f/s.z, 1.f/s.w);
    float* ob = Dw + b * Mt * NHt + c;
    #pragma unroll
    for (int m = 0; m < Mt; ++m) {
        float4 o = make_float4(v[m].x*inv.x, v[m].y*inv.y, v[m].z*inv.z, v[m].w*inv.w);
        *(float4*)(ob + m * NHt) = o;
    }
}

// ---------------- softmax_np ----------------
__global__ void softmax_np(const float* __restrict__ L, float* __restrict__ Cw)
{
    __shared__ float s[Ne * 688];
    const int bm  = blockIdx.x;
    const int tid = threadIdx.x;
    const float* Lrow = L + bm * NHt;

    for (int idx = tid; idx < NHt; idx += 256) {
        const int n = idx / Hh, p = idx - n * Hh;
        s[n * 688 + p] = Lrow[idx];
    }
    __syncthreads();

    for (int p = tid; p < Hh; p += 256) {
        float mx = -3.4e38f;
        #pragma unroll
        for (int n = 0; n < Ne; ++n) mx = fmaxf(mx, s[n * 688 + p]);
        float sum = 0.f;
        #pragma unroll
        for (int n = 0; n < Ne; ++n) {
            const float e = expf(s[n * 688 + p] - mx);
            s[n * 688 + p] = e;
            sum += e;
        }
        const float inv = 1.f / sum;
        #pragma unroll
        for (int n = 0; n < Ne; ++n) s[n * 688 + p] *= inv;
    }
    __syncthreads();

    const int warp = tid >> 5, lane = tid & 31;
    for (int n = warp; n < Ne; n += 8) {
        float mx = -3.4e38f;
        for (int p = lane; p < Hh; p += 32) mx = fmaxf(mx, s[n * 688 + p]);
        #pragma unroll
        for (int o = 16; o; o >>= 1) mx = fmaxf(mx, __shfl_xor_sync(0xffffffffu, mx, o));
        float sum = 0.f;
        for (int p = lane; p < Hh; p += 32) {
            const float e = expf(s[n * 688 + p] - mx);
            s[n * 688 + p] = e;
            sum += e;
        }
        #pragma unroll
        for (int o = 16; o; o >>= 1) sum += __shfl_xor_sync(0xffffffffu, sum, o);
        const float inv = 1.f / sum;
        for (int p = lane; p < Hh; p += 32)
            Cw[bm * NHt + n * Hh + p] = s[n * 688 + p] * inv;
    }
}

// ---------------- b2sum ----------------
__global__ void b2sum_k(const float* __restrict__ b2, float* __restrict__ b2s)
{
    const int d = blockIdx.x * blockDim.x + threadIdx.x;
    if (d < OUTD) {
        float s = 0.f;
        #pragma unroll
        for (int n = 0; n < Ne; ++n) s += b2[n * OUTD + d];
        b2s[d] = s;
    }
}

// ---------------- TENSOR fused mix -> relu -> combine ----------------
// Per block (b,n): G[m',h] = sum_p Cw[m',p] * relu( sum_m Dw[m,p]*XW1[m,h] + b1[h] )
// p-chunks of 16; warp w owns h-tiles {w, w+8, ...} (<= 11 n8-tiles); warp-independent main loop.
#define XH_STR 18
#define FG_SXH 0
#define FG_SXL (FG_SXH + 688*XH_STR*2)
#define FG_SHH (FG_SXL + 688*XH_STR*2)
#define FG_SHL (FG_SHH + 688*XH_STR*2)
#define FG_SB  (FG_SHL + 688*XH_STR*2)
#define FG_SMEM (FG_SB + 688*4)          /* 101824 */

__global__ __launch_bounds__(256) void fused_G_tc(const float* __restrict__ XW1,
                                                  const float* __restrict__ Dw,
                                                  const float* __restrict__ Cwp,
                                                  const float* __restrict__ b1,
                                                  bf16* __restrict__ gh,
                                                  bf16* __restrict__ gl)
{
    extern __shared__ __align__(16) char sm[];
    bf16*  sXh = (bf16*)(sm + FG_SXH);
    bf16*  sXl = (bf16*)(sm + FG_SXL);
    bf16*  sHh = (bf16*)(sm + FG_SHH);
    bf16*  sHl = (bf16*)(sm + FG_SHL);
    float* sb  = (float*)(sm + FG_SB);

    const int bx = blockIdx.x;
    const int n  = bx & (Ne - 1);
    const int b  = bx >> 4;
    const int t = threadIdx.x;
    const int w = t >> 5, lane = t & 31;
    const int gid = lane >> 2, qid = lane & 3;

    // ---- stage XW1 -> sX[h][m] bf16 hi/lo (zero-padded h>=682); bias -> sb
    for (int h = t; h < 688; h += 256) sb[h] = (h < Hh) ? b1[n * Hh + h] : 0.f;
    #pragma unroll 1
    for (int mm = 0; mm < Mt; ++mm) {
        const long long rb = ((long long)(b * Mt + mm) * Ne + n) * Hh;
        for (int h = t; h < 688; h += 256) {
            const float v = (h < Hh) ? XW1[rb + h] : 0.f;
            bf16 hi, lo; split2(v, hi, lo);
            sXh[h * XH_STR + mm] = hi;
            sXl[h * XH_STR + mm] = lo;
        }
    }
    __syncthreads();

    float acc[11][4];
    #pragma unroll
    for (int i = 0; i < 11; ++i)
        #pragma unroll
        for (int e = 0; e < 4; ++e) acc[i][e] = 0.f;

    const long long mstep = (long long)NHt;  // +1 in m => +Ne*Hh
    const int NCH = (Hh + 15) / 16;          // 43

    for (int c = 0; c < NCH; ++c) {
        const int P0 = c * 16;
        // ---- Dw A-fragments (A = Dw^T, row-major [p][m]) with hi/lo split
        const int pA = P0 + gid, pB = pA + 8;
        const bool vA = (pA < Hh), vB = (pB < Hh);
        const int m0 = qid * 2;
        const long long d0 = ((long long)(b * Mt + m0) * Ne + n) * Hh;
        uint32_t dah[4], dal[4];
        {
            float e00 = vA ? Dw[d0 + pA] : 0.f;
            float e01 = vA ? Dw[d0 + mstep + pA] : 0.f;
            float e10 = vB ? Dw[d0 + pB] : 0.f;
            float e11 = vB ? Dw[d0 + mstep + pB] : 0.f;
            float e20 = vA ? Dw[d0 + 8 * mstep + pA] : 0.f;
            float e21 = vA ? Dw[d0 + 9 * mstep + pA] : 0.f;
            float e30 = vB ? Dw[d0 + 8 * mstep + pB] : 0.f;
            float e31 = vB ? Dw[d0 + 9 * mstep + pB] : 0.f;
            pksp(e00, e01, dah[0], dal[0]);
            pksp(e10, e11, dah[1], dal[1]);
            pksp(e20, e21, dah[2], dal[2]);
            pksp(e30, e31, dah[3], dal[3]);
        }
        // ---- Cw A-fragments (A = Cw, row-major [m'][p])
        uint32_t cah[4], cal[4];
        {
            const long long c0r = ((long long)(b * Mt + gid) * Ne + n) * Hh;
            const long long c8r = c0r + 8 * mstep;
            const int k0 = P0 + qid * 2;
            const int k8 = k0 + 8;
            float e00 = (k0     < Hh) ? Cwp[c0r + k0]     : 0.f;
            float e01 = (k0 + 1 < Hh) ? Cwp[c0r + k0 + 1] : 0.f;
            float e10 = (k0     < Hh) ? Cwp[c8r + k0]     : 0.f;
            float e11 = (k0 + 1 < Hh) ? Cwp[c8r + k0 + 1] : 0.f;
            float e20 = (k8     < Hh) ? Cwp[c0r + k8]     : 0.f;
            float e21 = (k8 + 1 < Hh) ? Cwp[c0r + k8 + 1] : 0.f;
            float e30 = (k8     < Hh) ? Cwp[c8r + k8]     : 0.f;
            float e31 = (k8 + 1 < Hh) ? Cwp[c8r + k8 + 1] : 0.f;
            pksp(e00, e01, cah[0], cal[0]);
            pksp(e10, e11, cah[1], cal[1]);
            pksp(e20, e21, cah[2], cal[2]);
            pksp(e30, e31, cah[3], cal[3]);
        }

        // ---- stage 1: H[p=16][h] = Dw^T @ XW1, +bias, relu, split -> sH[h][p]
        #pragma unroll
        for (int ti = 0; ti < 11; ++ti) {
            const int tw = w + ti * 8;
            if (tw >= 86) break;
            const int hrow = tw * 8 + gid;
            const uint32_t xh0 = *(const uint32_t*)(sXh + hrow * XH_STR + qid * 2);
            const uint32_t xh1 = *(const uint32_t*)(sXh + hrow * XH_STR + qid * 2 + 8);
            const uint32_t xl0 = *(const uint32_t*)(sXl + hrow * XH_STR + qid * 2);
            const uint32_t xl1 = *(const uint32_t*)(sXl + hrow * XH_STR + qid * 2 + 8);
            float cf[4] = {0.f, 0.f, 0.f, 0.f};
            mma_bf16(cf, dah[0], dah[1], dah[2], dah[3], xh0, xh1);
            mma_bf16(cf, dah[0], dah[1], dah[2], dah[3], xl0, xl1);
            mma_bf16(cf, dal[0], dal[1], dal[2], dal[3], xh0, xh1);
            const int ha = tw * 8 + qid * 2, hb = ha + 1;
            const float ba = sb[ha], bb = sb[hb];
            const float v00 = fmaxf(cf[0] + ba, 0.f);
            const float v01 = fmaxf(cf[1] + bb, 0.f);
            const float v10 = fmaxf(cf[2] + ba, 0.f);
            const float v11 = fmaxf(cf[3] + bb, 0.f);
            bf16 hi, lo;
            split2(v00, hi, lo); sHh[ha * XH_STR + gid]     = hi; sHl[ha * XH_STR + gid]     = lo;
            split2(v01, hi, lo); sHh[hb * XH_STR + gid]     = hi; sHl[hb * XH_STR + gid]     = lo;
            split2(v10, hi, lo); sHh[ha * XH_STR + gid + 8] = hi; sHl[ha * XH_STR + gid + 8] = lo;
            split2(v11, hi, lo); sHh[hb * XH_STR + gid + 8] = hi; sHl[hb * XH_STR + gid + 8] = lo;
        }
        __syncwarp();

        // ---- stage 2: G[m'][h] += Cw_chunk @ H_chunk
        #pragma unroll
        for (int ti = 0; ti < 11; ++ti) {
            const int tw = w + ti * 8;
            if (tw >= 86) break;
            const int hrow = tw * 8 + gid;
            const uint32_t hh0 = *(const uint32_t*)(sHh + hrow * XH_STR + qid * 2);
            const uint32_t hh1 = *(const uint32_t*)(sHh + hrow * XH_STR + qid * 2 + 8);
            const uint32_t hl0 = *(const uint32_t*)(sHl + hrow * XH_STR + qid * 2);
            const uint32_t hl1 = *(const uint32_t*)(sHl + hrow * XH_STR + qid * 2 + 8);
            mma_bf16(acc[ti], cah[0], cah[1], cah[2], cah[3], hh0, hh1);
            mma_bf16(acc[ti], cah[0], cah[1], cah[2], cah[3], hl0, hl1);
            mma_bf16(acc[ti], cal[0], cal[1], cal[2], cal[3], hh0, hh1);
        }
        __syncwarp();
    }

    // ---- store G (bf16 hi/lo for Y GEMM)
    const long long g0 = ((long long)(b * Mt + gid) * Ne + n) * Hh;
    const long long g8 = g0 + 8 * mstep;
    #pragma unroll
    for (int ti = 0; ti < 11; ++ti) {
        const int tw = w + ti * 8;
        if (tw >= 86) break;
        const int ha = tw * 8 + qid * 2, hb = ha + 1;
        if (ha < Hh) {
            st_split(gh, gl, g0 + ha, acc[ti][0]);
            st_split(gh, gl, g8 + ha, acc[ti][2]);
        }
        if (hb < Hh) {
            st_split(gh, gl, g0 + hb, acc[ti][1]);
            st_split(gh, gl, g8 + hb, acc[ti][3]);
        }
    }
}

// ---------------- ypart_reduce ----------------
__global__ void ypart_reduce(const float* __restrict__ part, const float* __restrict__ b2s,
                             float* __restrict__ Y)
{
    const int i4 = blockIdx.x * blockDim.x + threadIdx.x;
    const int idx = i4 * 4;
    const int col = idx & (OUTD - 1);
    float4 s = *(const float4*)(b2s + col);
    #pragma unroll
    for (int z = 0; z < YSPLIT; ++z) {
        float4 p = *(const float4*)(part + z * (Rows * OUTD) + idx);
        s.x += p.x; s.y += p.y; s.z += p.z; s.w += p.w;
    }
    *(float4*)(Y + idx) = s;
}

// ---------------- output GEMM ----------------
__global__ __launch_bounds__(128) void out_partial(const float* __restrict__ Y,
                                                   const float* __restrict__ Wout,
                                                   float* __restrict__ part)
{
    constexpr int KC = (Mt * Dd) / OSPLIT;
    __shared__ float ys[Bb][KC];
    const int tid = threadIdx.x;
    const int col = tid * 4;
    const int k0  = blockIdx.y * KC;

    for (int idx = tid; idx < Bb * KC; idx += 128) {
        const int bi = idx / KC, kk = idx - bi * KC;
        ys[bi][kk] = Y[bi * (Mt * Dd) + k0 + kk];
    }
    __syncthreads();

    float4 acc[Bb];
    #pragma unroll
    for (int bi = 0; bi < Bb; ++bi) acc[bi] = make_float4(0.f,0.f,0.f,0.f);

    for (int kk = 0; kk < KC; ++kk) {
        const float4 w = *(const float4*)(Wout + (k0 + kk) * OUTD + col);
        #pragma unroll
        for (int bi = 0; bi < Bb; ++bi) {
            const float yv = ys[bi][kk];
            acc[bi].x = fmaf(yv, w.x, acc[bi].x);
            acc[bi].y = fmaf(yv, w.y, acc[bi].y);
            acc[bi].z = fmaf(yv, w.z, acc[bi].z);
            acc[bi].w = fmaf(yv, w.w, acc[bi].w);
        }
    }
    #pragma unroll
    for (int bi = 0; bi < Bb; ++bi)
        *(float4*)(part + (blockIdx.y * Bb + bi) * OUTD + col) = acc[bi];
}

__global__ void out_reduce(const float* __restrict__ part, const float* __restrict__ bout,
                           float* __restrict__ out)
{
    const int i4 = blockIdx.x * blockDim.x + threadIdx.x;
    const int idx = i4 * 4;
    const int col = idx & (OUTD - 1);
    const int bi  = idx >> 9;
    float4 s = *(const float4*)(bout + col);
    #pragma unroll
    for (int z = 0; z < OSPLIT; ++z) {
        float4 p = *(const float4*)(part + (z * Bb + bi) * OUTD + col);
        s.x += p.x; s.y += p.y; s.z += p.z; s.w += p.w;
    }
    *(float4*)(out + idx) = s;
}

// ---------------- launch ----------------
extern "C" void kernel_launch(void* const* d_in, const int* in_sizes, int n_in,
                              void* d_out, int out_size)
{
    const float* x    = (const float*)d_in[0];
    const float* phi  = (const float*)d_in[1];
    const float* W1   = (const float*)d_in[2];
    const float* b1   = (const float*)d_in[3];
    const float* W2   = (const float*)d_in[4];
    const float* b2   = (const float*)d_in[5];
    const float* Wout = (const float*)d_in[6];
    const float* bout = (const float*)d_in[7];
    float* out = (float*)d_out;

    float *p_logits, *p_Dw, *p_Cw, *p_XW1, *p_Ypart, *p_Y, *p_b2sum, *p_opart;
    bf16 *p_xh, *p_xl, *p_gh, *p_gl;
    cudaGetSymbolAddress((void**)&p_logits, g_logits);
    cudaGetSymbolAddress((void**)&p_Dw,     g_Dw);
    cudaGetSymbolAddress((void**)&p_Cw,     g_Cw);
    cudaGetSymbolAddress((void**)&p_XW1,    g_XW1);
    cudaGetSymbolAddress((void**)&p_Ypart,  g_Ypart);
    cudaGetSymbolAddress((void**)&p_Y,      g_Y);
    cudaGetSymbolAddress((void**)&p_b2sum,  g_b2sum);
    cudaGetSymbolAddress((void**)&p_opart,  g_opart);
    cudaGetSymbolAddress((void**)&p_xh,   g_xh);
    cudaGetSymbolAddress((void**)&p_xl,   g_xl);
    cudaGetSymbolAddress((void**)&p_gh,   g_gh);
    cudaGetSymbolAddress((void**)&p_gl,   g_gl);

    cudaFuncSetAttribute(mma_gemm<0>, cudaFuncAttributeMaxDynamicSharedMemorySize, MG_SMEM);
    cudaFuncSetAttribute(mma_gemm<1>, cudaFuncAttributeMaxDynamicSharedMemorySize, MG_SMEM);
    cudaFuncSetAttribute(fused_G_tc,  cudaFuncAttributeMaxDynamicSharedMemorySize, FG_SMEM);

    cvt_split<<<(Rows*Dd/4 + 255)/256, 256>>>(x, p_xh, p_xl, Rows*Dd/4);

    const dim3 gBig((NHt + 127)/128, Rows/64, 1);
    mma_gemm<0><<<gBig, 256, MG_SMEM>>>(p_xh, p_xl, phi, p_logits, NHt, Dd, 1);
    mma_gemm<1><<<gBig, 256, MG_SMEM>>>(p_xh, p_xl, W1,  p_XW1,    NHt, Dd, 1);

    softmax_m <<<(Bb*(NHt/4) + 255)/256, 256>>>(p_logits, p_Dw);
    softmax_np<<<Rows, 256>>>(p_logits, p_Cw);
    b2sum_k   <<<(OUTD + 255)/256, 256>>>(b2, p_b2sum);

    fused_G_tc<<<Bb*Ne, 256, FG_SMEM>>>(p_XW1, p_Dw, p_Cw, b1, p_gh, p_gl);

    const dim3 gY(OUTD/128, Rows/64, YSPLIT);
    mma_gemm<0><<<gY, 256, MG_SMEM>>>(p_gh, p_gl, W2, p_Ypart, OUTD, NHt, YSPLIT);
    ypart_reduce<<<(Rows*OUTD/4)/256, 256>>>(p_Ypart, p_b2sum, p_Y);

    const dim3 gO(1, OSPLIT, 1);
    out_partial<<<gO, 128>>>(p_Y, Wout, p_opart);
    out_reduce <<<(Bb*OUTD/4)/256, 256>>>(p_opart, bout, out);
}

// round 8
// speedup vs baseline: 1.1125x; 1.0604x over previous
#include <cuda_runtime.h>
#include <cuda_bf16.h>
#include <math.h>
#include <stdint.h>

#define Bb   16
#define Mt   16
#define Dd   512
#define Ne   16
#define Hh   682
#define NHt  (Ne*Hh)      /* 10912 */
#define Rows (Bb*Mt)      /* 256   */
#define OUTD 512
#define YSPLIT 16
#define OSPLIT 64

typedef unsigned long long ull;
typedef __nv_bfloat16 bf16;

// ---- warp mma: D(16x8 f32) += A(16x16 bf16) * B(16x8 bf16) ----
__device__ __forceinline__ void mma_bf16(float* c, uint32_t a0, uint32_t a1, uint32_t a2, uint32_t a3,
                                         uint32_t b0, uint32_t b1) {
    asm volatile("mma.sync.aligned.m16n8k16.row.col.f32.bf16.bf16.f32 "
        "{%0,%1,%2,%3}, {%4,%5,%6,%7}, {%8,%9}, {%0,%1,%2,%3};"
        : "+f"(c[0]), "+f"(c[1]), "+f"(c[2]), "+f"(c[3])
        : "r"(a0), "r"(a1), "r"(a2), "r"(a3), "r"(b0), "r"(b1));
}

__device__ __forceinline__ void split2(float v, bf16& h, bf16& l) {
    h = __float2bfloat16(v);
    l = __float2bfloat16(v - __bfloat162float(h));
}
__device__ __forceinline__ void st_split(bf16* gh, bf16* gl, long long idx, float v) {
    bf16 h, l; split2(v, h, l);
    gh[idx] = h; gl[idx] = l;
}
__device__ __forceinline__ void pksp(float x, float y, uint32_t& hr, uint32_t& lr) {
    bf16 hx, lx, hy, ly;
    split2(x, hx, lx); split2(y, hy, ly);
    __nv_bfloat162 H; H.x = hx; H.y = hy;
    __nv_bfloat162 L; L.x = lx; L.y = ly;
    hr = *(uint32_t*)&H; lr = *(uint32_t*)&L;
}

// ---------------- scratch ----------------
__device__ float g_logits[Rows*NHt];
__device__ float g_Cw[Rows*NHt];
__device__ float g_XW1[Rows*NHt];
__device__ float g_Ypart[YSPLIT*Rows*OUTD];
__device__ float g_Y[Rows*OUTD];
__device__ float g_b2sum[OUTD];
__device__ float g_opart[OSPLIT*Bb*OUTD];
__device__ bf16 g_xh[Rows*Dd],  g_xl[Rows*Dd];
__device__ bf16 g_gh[Rows*NHt], g_gl[Rows*NHt];

// ---------------- fp32 -> bf16 hi/lo split ----------------
__global__ void cvt_split(const float* __restrict__ src, bf16* __restrict__ hi,
                          bf16* __restrict__ lo, int n4)
{
    const int i = blockIdx.x * blockDim.x + threadIdx.x;
    if (i >= n4) return;
    const float4 v = ((const float4*)src)[i];
    bf16 h[4], l[4];
    const float vv[4] = {v.x, v.y, v.z, v.w};
    #pragma unroll
    for (int e = 0; e < 4; ++e) split2(vv[e], h[e], l[e]);
    *(ull*)(hi + i * 4) = *(const ull*)h;
    *(ull*)(lo + i * 4) = *(const ull*)l;
}

// ---------------- mma.sync bf16-split GEMM, Mtile=128 x Ntile=64 ----------------
// C(+split-K partials) [z][256][Nc] = A[256][K] @ B[K][Nc]
// A: pre-split bf16 hi/lo.  B: fp32 converted in-loader.
// MODE 0: B row-major [K, Nc].  MODE 1: B[k][j] = W1[n][k][h], j=n*Hh+h.
// 8 warps as 4m x 2n; warp tile 32x32; K-chunks of 64.
#define AS_STR 72
#define BS_STR 74
#define SM_AH 0
#define SM_AL (SM_AH + 128*AS_STR*2)     /* 18432 */
#define SM_BH (SM_AL + 128*AS_STR*2)     /* 36864 */
#define SM_BL (SM_BH + 64*BS_STR*2)      /* 46336 */
#define MG_SMEM (SM_BL + 64*BS_STR*2)    /* 55808 */

template<int MODE>
__global__ __launch_bounds__(256) void mma_gemm(
    const bf16* __restrict__ Ah, const bf16* __restrict__ Al,
    const float* __restrict__ Bm,
    float* __restrict__ C, int Nc, int K, int nsplit)
{
    extern __shared__ __align__(16) char sm[];
    bf16* sAh = (bf16*)(sm + SM_AH);
    bf16* sAl = (bf16*)(sm + SM_AL);
    bf16* sBh = (bf16*)(sm + SM_BH);
    bf16* sBl = (bf16*)(sm + SM_BL);

    const int t = threadIdx.x;
    const int lane = t & 31, warp = t >> 5;
    const int wm = (warp & 3) * 32;          // 4 m-warps
    const int wn = (warp >> 2) * 32;         // 2 n-warps
    const int m0 = blockIdx.y * 128;
    const int j0 = blockIdx.x * 64;
    const int z  = blockIdx.z;
    const int nch = (K + 63) >> 6;
    const int c0 = (int)((long long)nch * z / nsplit);
    const int c1 = (int)((long long)nch * (z + 1) / nsplit);

    float acc[2][4][4];
    #pragma unroll
    for (int i = 0; i < 2; ++i)
        #pragma unroll
        for (int j = 0; j < 4; ++j)
            #pragma unroll
            for (int e = 0; e < 4; ++e) acc[i][j][e] = 0.f;

    const int gid = lane >> 2;
    const int qid = lane & 3;

    int bn[4], bh[4];
    if (MODE == 1) {
        #pragma unroll
        for (int it = 0; it < 4; ++it) {
            const int g = (t + it * 256) & 15;
            const int j = j0 + g * 4;
            int n = j / Hh;
            bn[it] = n;
            bh[it] = j - n * Hh;
        }
    }

    for (int c = c0; c < c1; ++c) {
        const int k0 = c << 6;
        __syncthreads();
        // ---- A tiles: 128 rows x 64 k (8 iters)
        #pragma unroll
        for (int it = 0; it < 8; ++it) {
            const int s = t + it * 256;
            const int kq = s & 15;
            const int row = s >> 4;                  // 0..127
            const int gk = k0 + kq * 4;
            const long long ga = (long long)(m0 + row) * K + gk;
            ull vh = 0, vl = 0;
            if (gk + 4 <= K) { vh = *(const ull*)(Ah + ga); vl = *(const ull*)(Al + ga); }
            *(ull*)(sAh + row * AS_STR + kq * 4) = vh;
            *(ull*)(sAl + row * AS_STR + kq * 4) = vl;
        }
        // ---- B tiles: 64 k x 64 n, fp32 -> bf16 hi/lo, transposed to [n][k] (4 iters)
        #pragma unroll
        for (int it = 0; it < 4; ++it) {
            const int s = t + it * 256;
            const int g = s & 15;                    // n-quad 0..15
            const int k = s >> 4;                    // 0..63
            const int gj = j0 + g * 4;
            const int gk = k0 + k;
            float vv[4] = {0.f, 0.f, 0.f, 0.f};
            if (MODE == 0) {
                if (gj + 4 <= Nc && gk < K) {
                    const float4 v = *(const float4*)(Bm + (long long)gk * Nc + gj);
                    vv[0] = v.x; vv[1] = v.y; vv[2] = v.z; vv[3] = v.w;
                }
            } else {
                if (gk < K) {
                    int n = bn[it], h = bh[it];
                    #pragma unroll
                    for (int e = 0; e < 4; ++e) {
                        if (gj + e < Nc) vv[e] = Bm[((long long)n * K + gk) * Hh + h];
                        if (++h >= Hh) { h = 0; ++n; }
                    }
                }
            }
            #pragma unroll
            for (int e = 0; e < 4; ++e) {
                bf16 h, l; split2(vv[e], h, l);
                sBh[(g * 4 + e) * BS_STR + k] = h;
                sBl[(g * 4 + e) * BS_STR + k] = l;
            }
        }
        __syncthreads();

        #pragma unroll
        for (int ks = 0; ks < 4; ++ks) {
            const int kcol = ks * 16 + qid * 2;
            uint32_t ah[2][4], al[2][4];
            #pragma unroll
            for (int mi = 0; mi < 2; ++mi) {
                const int r = wm + mi * 16 + gid;
                ah[mi][0] = *(const uint32_t*)(sAh + r * AS_STR + kcol);
                ah[mi][1] = *(const uint32_t*)(sAh + (r + 8) * AS_STR + kcol);
                ah[mi][2] = *(const uint32_t*)(sAh + r * AS_STR + kcol + 8);
                ah[mi][3] = *(const uint32_t*)(sAh + (r + 8) * AS_STR + kcol + 8);
                al[mi][0] = *(const uint32_t*)(sAl + r * AS_STR + kcol);
                al[mi][1] = *(const uint32_t*)(sAl + (r + 8) * AS_STR + kcol);
                al[mi][2] = *(const uint32_t*)(sAl + r * AS_STR + kcol + 8);
                al[mi][3] = *(const uint32_t*)(sAl + (r + 8) * AS_STR + kcol + 8);
            }
            uint32_t bhf[4][2], blf[4][2];
            #pragma unroll
            for (int ni = 0; ni < 4; ++ni) {
                const int n = wn + ni * 8 + gid;
                bhf[ni][0] = *(const uint32_t*)(sBh + n * BS_STR + kcol);
                bhf[ni][1] = *(const uint32_t*)(sBh + n * BS_STR + kcol + 8);
                blf[ni][0] = *(const uint32_t*)(sBl + n * BS_STR + kcol);
                blf[ni][1] = *(const uint32_t*)(sBl + n * BS_STR + kcol + 8);
            }
            #pragma unroll
            for (int mi = 0; mi < 2; ++mi)
                #pragma unroll
                for (int ni = 0; ni < 4; ++ni) {
                    mma_bf16(acc[mi][ni], ah[mi][0], ah[mi][1], ah[mi][2], ah[mi][3],
                             bhf[ni][0], bhf[ni][1]);
                    mma_bf16(acc[mi][ni], ah[mi][0], ah[mi][1], ah[mi][2], ah[mi][3],
                             blf[ni][0], blf[ni][1]);
                    mma_bf16(acc[mi][ni], al[mi][0], al[mi][1], al[mi][2], al[mi][3],
                             bhf[ni][0], bhf[ni][1]);
                }
        }
    }

    float* Cz = C + (long long)z * Rows * Nc;
    #pragma unroll
    for (int mi = 0; mi < 2; ++mi) {
        const int r0 = m0 + wm + mi * 16 + gid;
        #pragma unroll
        for (int ni = 0; ni < 4; ++ni) {
            const int cn = j0 + wn + ni * 8 + qid * 2;
            if (cn < Nc) {
                float2 lo2 = make_float2(acc[mi][ni][0], acc[mi][ni][1]);
                float2 hi2 = make_float2(acc[mi][ni][2], acc[mi][ni][3]);
                *(float2*)(Cz + (long long)r0 * Nc + cn)       = lo2;
                *(float2*)(Cz + (long long)(r0 + 8) * Nc + cn) = hi2;
            }
        }
    }
}

// ---------------- softmax_np ----------------
__global__ void softmax_np(const float* __restrict__ L, float* __restrict__ Cw)
{
    __shared__ float s[Ne * 688];
    const int bm  = blockIdx.x;
    const int tid = threadIdx.x;
    const float* Lrow = L + bm * NHt;

    for (int idx = tid; idx < NHt; idx += 256) {
        const int n = idx / Hh, p = idx - n * Hh;
        s[n * 688 + p] = Lrow[idx];
    }
    __syncthreads();

    for (int p = tid; p < Hh; p += 256) {
        float mx = -3.4e38f;
        #pragma unroll
        for (int n = 0; n < Ne; ++n) mx = fmaxf(mx, s[n * 688 + p]);
        float sum = 0.f;
        #pragma unroll
        for (int n = 0; n < Ne; ++n) {
            const float e = expf(s[n * 688 + p] - mx);
            s[n * 688 + p] = e;
            sum += e;
        }
        const float inv = 1.f / sum;
        #pragma unroll
        for (int n = 0; n < Ne; ++n) s[n * 688 + p] *= inv;
    }
    __syncthreads();

    const int warp = tid >> 5, lane = tid & 31;
    for (int n = warp; n < Ne; n += 8) {
        float mx = -3.4e38f;
        for (int p = lane; p < Hh; p += 32) mx = fmaxf(mx, s[n * 688 + p]);
        #pragma unroll
        for (int o = 16; o; o >>= 1) mx = fmaxf(mx, __shfl_xor_sync(0xffffffffu, mx, o));
        float sum = 0.f;
        for (int p = lane; p < Hh; p += 32) {
            const float e = expf(s[n * 688 + p] - mx);
            s[n * 688 + p] = e;
            sum += e;
        }
        #pragma unroll
        for (int o = 16; o; o >>= 1) sum += __shfl_xor_sync(0xffffffffu, sum, o);
        const float inv = 1.f / sum;
        for (int p = lane; p < Hh; p += 32)
            Cw[bm * NHt + n * Hh + p] = s[n * 688 + p] * inv;
    }
}

// ---------------- b2sum ----------------
__global__ void b2sum_k(const float* __restrict__ b2, float* __restrict__ b2s)
{
    const int d = blockIdx.x * blockDim.x + threadIdx.x;
    if (d < OUTD) {
        float s = 0.f;
        #pragma unroll
        for (int n = 0; n < Ne; ++n) s += b2[n * OUTD + d];
        b2s[d] = s;
    }
}

// ---------------- TENSOR fused: inline Dw-softmax + mix -> relu -> combine ----------------
// Per block (b,n): Dw = softmax_m(logits slice); G[m',h] = sum_p Cw[m',p]*relu(sum_m Dw[m,p]*XW1[m,h]+b1[h])
#define XH_STR 18
#define FG_SXH 0
#define FG_SXL (FG_SXH + 688*XH_STR*2)
#define FG_SHH (FG_SXL + 688*XH_STR*2)
#define FG_SHL (FG_SHH + 688*XH_STR*2)
#define FG_SB   (FG_SHL + 688*XH_STR*2)
#define FG_SMX  (FG_SB  + 688*4)
#define FG_SINV (FG_SMX + 688*4)
#define FG_SMEM (FG_SINV + 688*4)       /* 107328 */

__global__ __launch_bounds__(256) void fused_G_tc(const float* __restrict__ XW1,
                                                  const float* __restrict__ Lg,
                                                  const float* __restrict__ Cwp,
                                                  const float* __restrict__ b1,
                                                  bf16* __restrict__ gh,
                                                  bf16* __restrict__ gl)
{
    extern __shared__ __align__(16) char sm[];
    bf16*  sXh = (bf16*)(sm + FG_SXH);
    bf16*  sXl = (bf16*)(sm + FG_SXL);
    bf16*  sHh = (bf16*)(sm + FG_SHH);
    bf16*  sHl = (bf16*)(sm + FG_SHL);
    float* sb   = (float*)(sm + FG_SB);
    float* smx  = (float*)(sm + FG_SMX);
    float* sinv = (float*)(sm + FG_SINV);

    const int bx = blockIdx.x;
    const int n  = bx & (Ne - 1);
    const int b  = bx >> 4;
    const int t = threadIdx.x;
    const int w = t >> 5, lane = t & 31;
    const int gid = lane >> 2, qid = lane & 3;
    const long long mstep = (long long)NHt;

    // ---- Dw softmax stats per p-column (over 16 m)
    for (int p = t; p < 688; p += 256) {
        if (p < Hh) {
            const long long base = ((long long)(b * Mt) * Ne + n) * Hh + p;
            float v[Mt], mx = -3.4e38f;
            #pragma unroll
            for (int m = 0; m < Mt; ++m) { v[m] = Lg[base + m * mstep]; mx = fmaxf(mx, v[m]); }
            float sum = 0.f;
            #pragma unroll
            for (int m = 0; m < Mt; ++m) sum += expf(v[m] - mx);
            smx[p] = mx; sinv[p] = 1.f / sum;
        } else { smx[p] = 0.f; sinv[p] = 0.f; }
        sb[p] = (p < Hh) ? b1[n * Hh + p] : 0.f;
    }

    // ---- stage XW1 -> sX[h][m] bf16 hi/lo
    #pragma unroll 1
    for (int mm = 0; mm < Mt; ++mm) {
        const long long rb = ((long long)(b * Mt + mm) * Ne + n) * Hh;
        for (int h = t; h < 688; h += 256) {
            const float v = (h < Hh) ? XW1[rb + h] : 0.f;
            bf16 hi, lo; split2(v, hi, lo);
            sXh[h * XH_STR + mm] = hi;
            sXl[h * XH_STR + mm] = lo;
        }
    }
    __syncthreads();

    float acc[11][4];
    #pragma unroll
    for (int i = 0; i < 11; ++i)
        #pragma unroll
        for (int e = 0; e < 4; ++e) acc[i][e] = 0.f;

    const int NCH = (Hh + 15) / 16;  // 43

    for (int c = 0; c < NCH; ++c) {
        const int P0 = c * 16;
        // ---- Dw A-fragments from logits + stats (A = Dw^T, [p][m])
        const int pA = P0 + gid, pB = pA + 8;
        const bool vA = (pA < Hh), vB = (pB < Hh);
        const int m0 = qid * 2;
        const long long d0 = ((long long)(b * Mt + m0) * Ne + n) * Hh;
        const float mxA = smx[pA], ivA = sinv[pA];
        const float mxB = smx[pB], ivB = sinv[pB];
        uint32_t dah[4], dal[4];
        {
            float e00 = vA ? expf(Lg[d0 + pA]             - mxA) * ivA : 0.f;
            float e01 = vA ? expf(Lg[d0 + mstep + pA]     - mxA) * ivA : 0.f;
            float e10 = vB ? expf(Lg[d0 + pB]             - mxB) * ivB : 0.f;
            float e11 = vB ? expf(Lg[d0 + mstep + pB]     - mxB) * ivB : 0.f;
            float e20 = vA ? expf(Lg[d0 + 8 * mstep + pA] - mxA) * ivA : 0.f;
            float e21 = vA ? expf(Lg[d0 + 9 * mstep + pA] - mxA) * ivA : 0.f;
            float e30 = vB ? expf(Lg[d0 + 8 * mstep + pB] - mxB) * ivB : 0.f;
            float e31 = vB ? expf(Lg[d0 + 9 * mstep + pB] - mxB) * ivB : 0.f;
            pksp(e00, e01, dah[0], dal[0]);
            pksp(e10, e11, dah[1], dal[1]);
            pksp(e20, e21, dah[2], dal[2]);
            pksp(e30, e31, dah[3], dal[3]);
        }
        // ---- Cw A-fragments (A = Cw, [m'][p])
        uint32_t cah[4], cal[4];
        {
            const long long c0r = ((long long)(b * Mt + gid) * Ne + n) * Hh;
            const long long c8r = c0r + 8 * mstep;
            const int k0 = P0 + qid * 2;
            const int k8 = k0 + 8;
            float e00 = (k0     < Hh) ? Cwp[c0r + k0]     : 0.f;
            float e01 = (k0 + 1 < Hh) ? Cwp[c0r + k0 + 1] : 0.f;
            float e10 = (k0     < Hh) ? Cwp[c8r + k0]     : 0.f;
            float e11 = (k0 + 1 < Hh) ? Cwp[c8r + k0 + 1] : 0.f;
            float e20 = (k8     < Hh) ? Cwp[c0r + k8]     : 0.f;
            float e21 = (k8 + 1 < Hh) ? Cwp[c0r + k8 + 1] : 0.f;
            float e30 = (k8     < Hh) ? Cwp[c8r + k8]     : 0.f;
            float e31 = (k8 + 1 < Hh) ? Cwp[c8r + k8 + 1] : 0.f;
            pksp(e00, e01, cah[0], cal[0]);
            pksp(e10, e11, cah[1], cal[1]);
            pksp(e20, e21, cah[2], cal[2]);
            pksp(e30, e31, cah[3], cal[3]);
        }

        // ---- stage 1: H = Dw^T @ XW1, +bias, relu -> sH[h][p]
        #pragma unroll
        for (int ti = 0; ti < 11; ++ti) {
            const int tw = w + ti * 8;
            if (tw >= 86) break;
            const int hrow = tw * 8 + gid;
            const uint32_t xh0 = *(const uint32_t*)(sXh + hrow * XH_STR + qid * 2);
            const uint32_t xh1 = *(const uint32_t*)(sXh + hrow * XH_STR + qid * 2 + 8);
            const uint32_t xl0 = *(const uint32_t*)(sXl + hrow * XH_STR + qid * 2);
            const uint32_t xl1 = *(const uint32_t*)(sXl + hrow * XH_STR + qid * 2 + 8);
            float cf[4] = {0.f, 0.f, 0.f, 0.f};
            mma_bf16(cf, dah[0], dah[1], dah[2], dah[3], xh0, xh1);
            mma_bf16(cf, dah[0], dah[1], dah[2], dah[3], xl0, xl1);
            mma_bf16(cf, dal[0], dal[1], dal[2], dal[3], xh0, xh1);
            const int ha = tw * 8 + qid * 2, hb = ha + 1;
            const float ba = sb[ha], bb = sb[hb];
            const float v00 = fmaxf(cf[0] + ba, 0.f);
            const float v01 = fmaxf(cf[1] + bb, 0.f);
            const float v10 = fmaxf(cf[2] + ba, 0.f);
            const float v11 = fmaxf(cf[3] + bb, 0.f);
            bf16 hi, lo;
            split2(v00, hi, lo); sHh[ha * XH_STR + gid]     = hi; sHl[ha * XH_STR + gid]     = lo;
            split2(v01, hi, lo); sHh[hb * XH_STR + gid]     = hi; sHl[hb * XH_STR + gid]     = lo;
            split2(v10, hi, lo); sHh[ha * XH_STR + gid + 8] = hi; sHl[ha * XH_STR + gid + 8] = lo;
            split2(v11, hi, lo); sHh[hb * XH_STR + gid + 8] = hi; sHl[hb * XH_STR + gid + 8] = lo;
        }
        __syncwarp();

        // ---- stage 2: G += Cw_chunk @ H_chunk
        #pragma unroll
        for (int ti = 0; ti < 11; ++ti) {
            const int tw = w + ti * 8;
            if (tw >= 86) break;
            const int hrow = tw * 8 + gid;
            const uint32_t hh0 = *(const uint32_t*)(sHh + hrow * XH_STR + qid * 2);
            const uint32_t hh1 = *(const uint32_t*)(sHh + hrow * XH_STR + qid * 2 + 8);
            const uint32_t hl0 = *(const uint32_t*)(sHl + hrow * XH_STR + qid * 2);
            const uint32_t hl1 = *(const uint32_t*)(sHl + hrow * XH_STR + qid * 2 + 8);
            mma_bf16(acc[ti], cah[0], cah[1], cah[2], cah[3], hh0, hh1);
            mma_bf16(acc[ti], cah[0], cah[1], cah[2], cah[3], hl0, hl1);
            mma_bf16(acc[ti], cal[0], cal[1], cal[2], cal[3], hh0, hh1);
        }
        __syncwarp();
    }

    // ---- store G (bf16 hi/lo)
    const long long g0 = ((long long)(b * Mt + gid) * Ne + n) * Hh;
    const long long g8 = g0 + 8 * mstep;
    #pragma unroll
    for (int ti = 0; ti < 11; ++ti) {
        const int tw = w + ti * 8;
        if (tw >= 86) break;
        const int ha = tw * 8 + qid * 2, hb = ha + 1;
        if (ha < Hh) {
            st_split(gh, gl, g0 + ha, acc[ti][0]);
            st_split(gh, gl, g8 + ha, acc[ti][2]);
        }
        if (hb < Hh) {
            st_split(gh, gl, g0 + hb, acc[ti][1]);
            st_split(gh, gl, g8 + hb, acc[ti][3]);
        }
    }
}

// ---------------- ypart_reduce ----------------
__global__ void ypart_reduce(const float* __restrict__ part, const float* __restrict__ b2s,
                             float* __restrict__ Y)
{
    const int i4 = blockIdx.x * blockDim.x + threadIdx.x;
    const int idx = i4 * 4;
    const int col = idx & (OUTD - 1);
    float4 s = *(const float4*)(b2s + col);
    #pragma unroll
    for (int z = 0; z < YSPLIT; ++z) {
        float4 p = *(const float4*)(part + z * (Rows * OUTD) + idx);
        s.x += p.x; s.y += p.y; s.z += p.z; s.w += p.w;
    }
    *(float4*)(Y + idx) = s;
}

// ---------------- output GEMM ----------------
__global__ __launch_bounds__(128) void out_partial(const float* __restrict__ Y,
                                                   const float* __restrict__ Wout,
                                                   float* __restrict__ part)
{
    constexpr int KC = (Mt * Dd) / OSPLIT;
    __shared__ float ys[Bb][KC];
    const int tid = threadIdx.x;
    const int col = tid * 4;
    const int k0  = blockIdx.y * KC;

    for (int idx = tid; idx < Bb * KC; idx += 128) {
        const int bi = idx / KC, kk = idx - bi * KC;
        ys[bi][kk] = Y[bi * (Mt * Dd) + k0 + kk];
    }
    __syncthreads();

    float4 acc[Bb];
    #pragma unroll
    for (int bi = 0; bi < Bb; ++bi) acc[bi] = make_float4(0.f,0.f,0.f,0.f);

    for (int kk = 0; kk < KC; ++kk) {
        const float4 w = *(const float4*)(Wout + (k0 + kk) * OUTD + col);
        #pragma unroll
        for (int bi = 0; bi < Bb; ++bi) {
            const float yv = ys[bi][kk];
            acc[bi].x = fmaf(yv, w.x, acc[bi].x);
            acc[bi].y = fmaf(yv, w.y, acc[bi].y);
            acc[bi].z = fmaf(yv, w.z, acc[bi].z);
            acc[bi].w = fmaf(yv, w.w, acc[bi].w);
        }
    }
    #pragma unroll
    for (int bi = 0; bi < Bb; ++bi)
        *(float4*)(part + (blockIdx.y * Bb + bi) * OUTD + col) = acc[bi];
}

__global__ void out_reduce(const float* __restrict__ part, const float* __restrict__ bout,
                           float* __restrict__ out)
{
    const int i4 = blockIdx.x * blockDim.x + threadIdx.x;
    const int idx = i4 * 4;
    const int col = idx & (OUTD - 1);
    const int bi  = idx >> 9;
    float4 s = *(const float4*)(bout + col);
    #pragma unroll
    for (int z = 0; z < OSPLIT; ++z) {
        float4 p = *(const float4*)(part + (z * Bb + bi) * OUTD + col);
        s.x += p.x; s.y += p.y; s.z += p.z; s.w += p.w;
    }
    *(float4*)(out + idx) = s;
}

// ---------------- launch ----------------
extern "C" void kernel_launch(void* const* d_in, const int* in_sizes, int n_in,
                              void* d_out, int out_size)
{
    const float* x    = (const float*)d_in[0];
    const float* phi  = (const float*)d_in[1];
    const float* W1   = (const float*)d_in[2];
    const float* b1   = (const float*)d_in[3];
    const float* W2   = (const float*)d_in[4];
    const float* b2   = (const float*)d_in[5];
    const float* Wout = (const float*)d_in[6];
    const float* bout = (const float*)d_in[7];
    float* out = (float*)d_out;

    float *p_logits, *p_Cw, *p_XW1, *p_Ypart, *p_Y, *p_b2sum, *p_opart;
    bf16 *p_xh, *p_xl, *p_gh, *p_gl;
    cudaGetSymbolAddress((void**)&p_logits, g_logits);
    cudaGetSymbolAddress((void**)&p_Cw,     g_Cw);
    cudaGetSymbolAddress((void**)&p_XW1,    g_XW1);
    cudaGetSymbolAddress((void**)&p_Ypart,  g_Ypart);
    cudaGetSymbolAddress((void**)&p_Y,      g_Y);
    cudaGetSymbolAddress((void**)&p_b2sum,  g_b2sum);
    cudaGetSymbolAddress((void**)&p_opart,  g_opart);
    cudaGetSymbolAddress((void**)&p_xh,   g_xh);
    cudaGetSymbolAddress((void**)&p_xl,   g_xl);
    cudaGetSymbolAddress((void**)&p_gh,   g_gh);
    cudaGetSymbolAddress((void**)&p_gl,   g_gl);

    cudaFuncSetAttribute(mma_gemm<0>, cudaFuncAttributeMaxDynamicSharedMemorySize, MG_SMEM);
    cudaFuncSetAttribute(mma_gemm<1>, cudaFuncAttributeMaxDynamicSharedMemorySize, MG_SMEM);
    cudaFuncSetAttribute(fused_G_tc,  cudaFuncAttributeMaxDynamicSharedMemorySize, FG_SMEM);

    cvt_split<<<(Rows*Dd/4 + 255)/256, 256>>>(x, p_xh, p_xl, Rows*Dd/4);

    const dim3 gBig((NHt + 63)/64, Rows/128, 1);             // 171 x 2
    mma_gemm<0><<<gBig, 256, MG_SMEM>>>(p_xh, p_xl, phi, p_logits, NHt, Dd, 1);
    mma_gemm<1><<<gBig, 256, MG_SMEM>>>(p_xh, p_xl, W1,  p_XW1,    NHt, Dd, 1);

    softmax_np<<<Rows, 256>>>(p_logits, p_Cw);
    b2sum_k   <<<(OUTD + 255)/256, 256>>>(b2, p_b2sum);

    fused_G_tc<<<Bb*Ne, 256, FG_SMEM>>>(p_XW1, p_logits, p_Cw, b1, p_gh, p_gl);

    const dim3 gY(OUTD/64, Rows/128, YSPLIT);                // 8 x 2 x 16
    mma_gemm<0><<<gY, 256, MG_SMEM>>>(p_gh, p_gl, W2, p_Ypart, OUTD, NHt, YSPLIT);
    ypart_reduce<<<(Rows*OUTD/4)/256, 256>>>(p_Ypart, p_b2sum, p_Y);

    const dim3 gO(1, OSPLIT, 1);
    out_partial<<<gO, 128>>>(p_Y, Wout, p_opart);
    out_reduce <<<(Bb*OUTD/4)/256, 256>>>(p_opart, bout, out);
}

// round 9
// speedup vs baseline: 1.1341x; 1.0195x over previous
#include <cuda_runtime.h>
#include <cuda_bf16.h>
#include <math.h>
#include <stdint.h>

#define Bb   16
#define Mt   16
#define Dd   512
#define Ne   16
#define Hh   682
#define NHt  (Ne*Hh)      /* 10912 */
#define Rows (Bb*Mt)      /* 256   */
#define OUTD 512
#define YSPLIT 16
#define OSPLIT 64

typedef unsigned long long ull;
typedef __nv_bfloat16 bf16;

// ---- warp mma: D(16x8 f32) += A(16x16 bf16) * B(16x8 bf16) ----
__device__ __forceinline__ void mma_bf16(float* c, uint32_t a0, uint32_t a1, uint32_t a2, uint32_t a3,
                                         uint32_t b0, uint32_t b1) {
    asm volatile("mma.sync.aligned.m16n8k16.row.col.f32.bf16.bf16.f32 "
        "{%0,%1,%2,%3}, {%4,%5,%6,%7}, {%8,%9}, {%0,%1,%2,%3};"
        : "+f"(c[0]), "+f"(c[1]), "+f"(c[2]), "+f"(c[3])
        : "r"(a0), "r"(a1), "r"(a2), "r"(a3), "r"(b0), "r"(b1));
}

__device__ __forceinline__ void split2(float v, bf16& h, bf16& l) {
    h = __float2bfloat16(v);
    l = __float2bfloat16(v - __bfloat162float(h));
}
__device__ __forceinline__ void st_split(bf16* gh, bf16* gl, long long idx, float v) {
    bf16 h, l; split2(v, h, l);
    gh[idx] = h; gl[idx] = l;
}
__device__ __forceinline__ void pksp(float x, float y, uint32_t& hr, uint32_t& lr) {
    bf16 hx, lx, hy, ly;
    split2(x, hx, lx); split2(y, hy, ly);
    __nv_bfloat162 H; H.x = hx; H.y = hy;
    __nv_bfloat162 L; L.x = lx; L.y = ly;
    hr = *(uint32_t*)&H; lr = *(uint32_t*)&L;
}

// ---------------- scratch ----------------
__device__ float g_logits[Rows*NHt];
__device__ float g_XW1[Rows*NHt];
__device__ float g_Ypart[YSPLIT*Rows*OUTD];
__device__ float g_Y[Rows*OUTD];
__device__ float g_b2sum[OUTD];
__device__ float g_opart[OSPLIT*Bb*OUTD];
__device__ bf16 g_xh[Rows*Dd],  g_xl[Rows*Dd];
__device__ bf16 g_gh[Rows*NHt], g_gl[Rows*NHt];
__device__ bf16 g_chh[Rows*NHt], g_chl[Rows*NHt];   // Cw pre-split bf16 hi/lo

// ---------------- prep: x split + b2sum in one kernel ----------------
#define CVT_BLOCKS (Rows*Dd/4/256)      /* 128 */
__global__ void prep_k(const float* __restrict__ src, bf16* __restrict__ hi,
                       bf16* __restrict__ lo, const float* __restrict__ b2,
                       float* __restrict__ b2s)
{
    const int bx = blockIdx.x;
    if (bx < CVT_BLOCKS) {
        const int i = bx * 256 + threadIdx.x;
        const float4 v = ((const float4*)src)[i];
        bf16 h[4], l[4];
        const float vv[4] = {v.x, v.y, v.z, v.w};
        #pragma unroll
        for (int e = 0; e < 4; ++e) split2(vv[e], h[e], l[e]);
        *(ull*)(hi + i * 4) = *(const ull*)h;
        *(ull*)(lo + i * 4) = *(const ull*)l;
    } else {
        const int d = (bx - CVT_BLOCKS) * 256 + threadIdx.x;
        if (d < OUTD) {
            float s = 0.f;
            #pragma unroll
            for (int n = 0; n < Ne; ++n) s += b2[n * OUTD + d];
            b2s[d] = s;
        }
    }
}

// ---------------- mma.sync bf16-split GEMM, Mtile=128 x Ntile=64 ----------------
#define AS_STR 72
#define BS_STR 74
#define SM_AH 0
#define SM_AL (SM_AH + 128*AS_STR*2)
#define SM_BH (SM_AL + 128*AS_STR*2)
#define SM_BL (SM_BH + 64*BS_STR*2)
#define MG_SMEM (SM_BL + 64*BS_STR*2)    /* 55808 */

template<int MODE>
__global__ __launch_bounds__(256) void mma_gemm(
    const bf16* __restrict__ Ah, const bf16* __restrict__ Al,
    const float* __restrict__ Bm,
    float* __restrict__ C, int Nc, int K, int nsplit)
{
    extern __shared__ __align__(16) char sm[];
    bf16* sAh = (bf16*)(sm + SM_AH);
    bf16* sAl = (bf16*)(sm + SM_AL);
    bf16* sBh = (bf16*)(sm + SM_BH);
    bf16* sBl = (bf16*)(sm + SM_BL);

    const int t = threadIdx.x;
    const int lane = t & 31, warp = t >> 5;
    const int wm = (warp & 3) * 32;
    const int wn = (warp >> 2) * 32;
    const int m0 = blockIdx.y * 128;
    const int j0 = blockIdx.x * 64;
    const int z  = blockIdx.z;
    const int nch = (K + 63) >> 6;
    const int c0 = (int)((long long)nch * z / nsplit);
    const int c1 = (int)((long long)nch * (z + 1) / nsplit);

    float acc[2][4][4];
    #pragma unroll
    for (int i = 0; i < 2; ++i)
        #pragma unroll
        for (int j = 0; j < 4; ++j)
            #pragma unroll
            for (int e = 0; e < 4; ++e) acc[i][j][e] = 0.f;

    const int gid = lane >> 2;
    const int qid = lane & 3;

    int bn[4], bh[4];
    if (MODE == 1) {
        #pragma unroll
        for (int it = 0; it < 4; ++it) {
            const int g = (t + it * 256) & 15;
            const int j = j0 + g * 4;
            int n = j / Hh;
            bn[it] = n;
            bh[it] = j - n * Hh;
        }
    }

    for (int c = c0; c < c1; ++c) {
        const int k0 = c << 6;
        __syncthreads();
        #pragma unroll
        for (int it = 0; it < 8; ++it) {
            const int s = t + it * 256;
            const int kq = s & 15;
            const int row = s >> 4;
            const int gk = k0 + kq * 4;
            const long long ga = (long long)(m0 + row) * K + gk;
            ull vh = 0, vl = 0;
            if (gk + 4 <= K) { vh = *(const ull*)(Ah + ga); vl = *(const ull*)(Al + ga); }
            *(ull*)(sAh + row * AS_STR + kq * 4) = vh;
            *(ull*)(sAl + row * AS_STR + kq * 4) = vl;
        }
        #pragma unroll
        for (int it = 0; it < 4; ++it) {
            const int s = t + it * 256;
            const int g = s & 15;
            const int k = s >> 4;
            const int gj = j0 + g * 4;
            const int gk = k0 + k;
            float vv[4] = {0.f, 0.f, 0.f, 0.f};
            if (MODE == 0) {
                if (gj + 4 <= Nc && gk < K) {
                    const float4 v = *(const float4*)(Bm + (long long)gk * Nc + gj);
                    vv[0] = v.x; vv[1] = v.y; vv[2] = v.z; vv[3] = v.w;
                }
            } else {
                if (gk < K) {
                    int n = bn[it], h = bh[it];
                    #pragma unroll
                    for (int e = 0; e < 4; ++e) {
                        if (gj + e < Nc) vv[e] = Bm[((long long)n * K + gk) * Hh + h];
                        if (++h >= Hh) { h = 0; ++n; }
                    }
                }
            }
            #pragma unroll
            for (int e = 0; e < 4; ++e) {
                bf16 h, l; split2(vv[e], h, l);
                sBh[(g * 4 + e) * BS_STR + k] = h;
                sBl[(g * 4 + e) * BS_STR + k] = l;
            }
        }
        __syncthreads();

        #pragma unroll
        for (int ks = 0; ks < 4; ++ks) {
            const int kcol = ks * 16 + qid * 2;
            uint32_t ah[2][4], al[2][4];
            #pragma unroll
            for (int mi = 0; mi < 2; ++mi) {
                const int r = wm + mi * 16 + gid;
                ah[mi][0] = *(const uint32_t*)(sAh + r * AS_STR + kcol);
                ah[mi][1] = *(const uint32_t*)(sAh + (r + 8) * AS_STR + kcol);
                ah[mi][2] = *(const uint32_t*)(sAh + r * AS_STR + kcol + 8);
                ah[mi][3] = *(const uint32_t*)(sAh + (r + 8) * AS_STR + kcol + 8);
                al[mi][0] = *(const uint32_t*)(sAl + r * AS_STR + kcol);
                al[mi][1] = *(const uint32_t*)(sAl + (r + 8) * AS_STR + kcol);
                al[mi][2] = *(const uint32_t*)(sAl + r * AS_STR + kcol + 8);
                al[mi][3] = *(const uint32_t*)(sAl + (r + 8) * AS_STR + kcol + 8);
            }
            uint32_t bhf[4][2], blf[4][2];
            #pragma unroll
            for (int ni = 0; ni < 4; ++ni) {
                const int n = wn + ni * 8 + gid;
                bhf[ni][0] = *(const uint32_t*)(sBh + n * BS_STR + kcol);
                bhf[ni][1] = *(const uint32_t*)(sBh + n * BS_STR + kcol + 8);
                blf[ni][0] = *(const uint32_t*)(sBl + n * BS_STR + kcol);
                blf[ni][1] = *(const uint32_t*)(sBl + n * BS_STR + kcol + 8);
            }
            #pragma unroll
            for (int mi = 0; mi < 2; ++mi)
                #pragma unroll
                for (int ni = 0; ni < 4; ++ni) {
                    mma_bf16(acc[mi][ni], ah[mi][0], ah[mi][1], ah[mi][2], ah[mi][3],
                             bhf[ni][0], bhf[ni][1]);
                    mma_bf16(acc[mi][ni], ah[mi][0], ah[mi][1], ah[mi][2], ah[mi][3],
                             blf[ni][0], blf[ni][1]);
                    mma_bf16(acc[mi][ni], al[mi][0], al[mi][1], al[mi][2], al[mi][3],
                             bhf[ni][0], bhf[ni][1]);
                }
        }
    }

    float* Cz = C + (long long)z * Rows * Nc;
    #pragma unroll
    for (int mi = 0; mi < 2; ++mi) {
        const int r0 = m0 + wm + mi * 16 + gid;
        #pragma unroll
        for (int ni = 0; ni < 4; ++ni) {
            const int cn = j0 + wn + ni * 8 + qid * 2;
            if (cn < Nc) {
                float2 lo2 = make_float2(acc[mi][ni][0], acc[mi][ni][1]);
                float2 hi2 = make_float2(acc[mi][ni][2], acc[mi][ni][3]);
                *(float2*)(Cz + (long long)r0 * Nc + cn)       = lo2;
                *(float2*)(Cz + (long long)(r0 + 8) * Nc + cn) = hi2;
            }
        }
    }
}

// ---------------- softmax_np: Cw = softmax_p(softmax_n(L)) -> bf16 hi/lo ----------------
__global__ void softmax_np(const float* __restrict__ L, bf16* __restrict__ chh,
                           bf16* __restrict__ chl)
{
    __shared__ float s[Ne * 688];
    const int bm  = blockIdx.x;
    const int tid = threadIdx.x;
    const float* Lrow = L + bm * NHt;

    // vectorized load: NHt = 2728 float4
    for (int i4 = tid; i4 < NHt / 4; i4 += 256) {
        const float4 v = *(const float4*)(Lrow + i4 * 4);
        const int idx = i4 * 4;
        const int n = idx / Hh;
        const int p = idx - n * Hh;
        // 4 consecutive idx may cross an n boundary (Hh=682 not mult of 4)
        float vv[4] = {v.x, v.y, v.z, v.w};
        int nn = n, pp = p;
        #pragma unroll
        for (int e = 0; e < 4; ++e) {
            s[nn * 688 + pp] = vv[e];
            if (++pp >= Hh) { pp = 0; ++nn; }
        }
    }
    __syncthreads();

    for (int p = tid; p < Hh; p += 256) {
        float mx = -3.4e38f;
        #pragma unroll
        for (int n = 0; n < Ne; ++n) mx = fmaxf(mx, s[n * 688 + p]);
        float sum = 0.f;
        #pragma unroll
        for (int n = 0; n < Ne; ++n) {
            const float e = expf(s[n * 688 + p] - mx);
            s[n * 688 + p] = e;
            sum += e;
        }
        const float inv = 1.f / sum;
        #pragma unroll
        for (int n = 0; n < Ne; ++n) s[n * 688 + p] *= inv;
    }
    __syncthreads();

    const int warp = tid >> 5, lane = tid & 31;
    for (int n = warp; n < Ne; n += 8) {
        float mx = -3.4e38f;
        for (int p = lane; p < Hh; p += 32) mx = fmaxf(mx, s[n * 688 + p]);
        #pragma unroll
        for (int o = 16; o; o >>= 1) mx = fmaxf(mx, __shfl_xor_sync(0xffffffffu, mx, o));
        float sum = 0.f;
        for (int p = lane; p < Hh; p += 32) {
            const float e = expf(s[n * 688 + p] - mx);
            s[n * 688 + p] = e;
            sum += e;
        }
        #pragma unroll
        for (int o = 16; o; o >>= 1) sum += __shfl_xor_sync(0xffffffffu, sum, o);
        const float inv = 1.f / sum;
        for (int p = lane; p < Hh; p += 32) {
            bf16 h, l; split2(s[n * 688 + p] * inv, h, l);
            const long long o2 = (long long)bm * NHt + n * Hh + p;
            chh[o2] = h; chl[o2] = l;
        }
    }
}

// ---------------- TENSOR fused: inline Dw-softmax + mix -> relu -> combine ----------------
#define XH_STR 18
#define FG_SXH 0
#define FG_SXL (FG_SXH + 688*XH_STR*2)
#define FG_SHH (FG_SXL + 688*XH_STR*2)
#define FG_SHL (FG_SHH + 688*XH_STR*2)
#define FG_SB   (FG_SHL + 688*XH_STR*2)
#define FG_SMX  (FG_SB  + 688*4)
#define FG_SINV (FG_SMX + 688*4)
#define FG_SMEM (FG_SINV + 688*4)       /* 107328 */

__global__ __launch_bounds__(256) void fused_G_tc(const float* __restrict__ XW1,
                                                  const float* __restrict__ Lg,
                                                  const bf16* __restrict__ chh,
                                                  const bf16* __restrict__ chl,
                                                  const float* __restrict__ b1,
                                                  bf16* __restrict__ gh,
                                                  bf16* __restrict__ gl)
{
    extern __shared__ __align__(16) char sm[];
    bf16*  sXh = (bf16*)(sm + FG_SXH);
    bf16*  sXl = (bf16*)(sm + FG_SXL);
    bf16*  sHh = (bf16*)(sm + FG_SHH);
    bf16*  sHl = (bf16*)(sm + FG_SHL);
    float* sb   = (float*)(sm + FG_SB);
    float* smx  = (float*)(sm + FG_SMX);
    float* sinv = (float*)(sm + FG_SINV);

    const int bx = blockIdx.x;
    const int n  = bx & (Ne - 1);
    const int b  = bx >> 4;
    const int t = threadIdx.x;
    const int w = t >> 5, lane = t & 31;
    const int gid = lane >> 2, qid = lane & 3;
    const long long mstep = (long long)NHt;

    // ---- Dw softmax stats per p-column (over 16 m)
    for (int p = t; p < 688; p += 256) {
        if (p < Hh) {
            const long long base = ((long long)(b * Mt) * Ne + n) * Hh + p;
            float v[Mt], mx = -3.4e38f;
            #pragma unroll
            for (int m = 0; m < Mt; ++m) { v[m] = Lg[base + m * mstep]; mx = fmaxf(mx, v[m]); }
            float sum = 0.f;
            #pragma unroll
            for (int m = 0; m < Mt; ++m) sum += expf(v[m] - mx);
            smx[p] = mx; sinv[p] = 1.f / sum;
        } else { smx[p] = 0.f; sinv[p] = 0.f; }
        sb[p] = (p < Hh) ? b1[n * Hh + p] : 0.f;
    }

    // ---- stage XW1 -> sX[h][m] bf16 hi/lo
    #pragma unroll 1
    for (int mm = 0; mm < Mt; ++mm) {
        const long long rb = ((long long)(b * Mt + mm) * Ne + n) * Hh;
        for (int h = t; h < 688; h += 256) {
            const float v = (h < Hh) ? XW1[rb + h] : 0.f;
            bf16 hi, lo; split2(v, hi, lo);
            sXh[h * XH_STR + mm] = hi;
            sXl[h * XH_STR + mm] = lo;
        }
    }
    __syncthreads();

    float acc[11][4];
    #pragma unroll
    for (int i = 0; i < 11; ++i)
        #pragma unroll
        for (int e = 0; e < 4; ++e) acc[i][e] = 0.f;

    const int NCH = (Hh + 15) / 16;  // 43

    for (int c = 0; c < NCH; ++c) {
        const int P0 = c * 16;
        // ---- Dw A-fragments from logits + stats (A = Dw^T, [p][m])
        const int pA = P0 + gid, pB = pA + 8;
        const bool vA = (pA < Hh), vB = (pB < Hh);
        const int m0 = qid * 2;
        const long long d0 = ((long long)(b * Mt + m0) * Ne + n) * Hh;
        const float mxA = smx[pA], ivA = sinv[pA];
        const float mxB = smx[pB], ivB = sinv[pB];
        uint32_t dah[4], dal[4];
        {
            float e00 = vA ? expf(Lg[d0 + pA]             - mxA) * ivA : 0.f;
            float e01 = vA ? expf(Lg[d0 + mstep + pA]     - mxA) * ivA : 0.f;
            float e10 = vB ? expf(Lg[d0 + pB]             - mxB) * ivB : 0.f;
            float e11 = vB ? expf(Lg[d0 + mstep + pB]     - mxB) * ivB : 0.f;
            float e20 = vA ? expf(Lg[d0 + 8 * mstep + pA] - mxA) * ivA : 0.f;
            float e21 = vA ? expf(Lg[d0 + 9 * mstep + pA] - mxA) * ivA : 0.f;
            float e30 = vB ? expf(Lg[d0 + 8 * mstep + pB] - mxB) * ivB : 0.f;
            float e31 = vB ? expf(Lg[d0 + 9 * mstep + pB] - mxB) * ivB : 0.f;
            pksp(e00, e01, dah[0], dal[0]);
            pksp(e10, e11, dah[1], dal[1]);
            pksp(e20, e21, dah[2], dal[2]);
            pksp(e30, e31, dah[3], dal[3]);
        }
        // ---- Cw A-fragments: direct uint32 loads from pre-split bf16 ([m'][p] pairs along p)
        uint32_t cah[4], cal[4];
        {
            const long long c0r = ((long long)(b * Mt + gid) * Ne + n) * Hh;
            const long long c8r = c0r + 8 * mstep;
            const int k0 = P0 + qid * 2;
            const int k8 = k0 + 8;
            if (k0 + 1 < Hh) {
                cah[0] = *(const uint32_t*)(chh + c0r + k0);
                cal[0] = *(const uint32_t*)(chl + c0r + k0);
                cah[1] = *(const uint32_t*)(chh + c8r + k0);
                cal[1] = *(const uint32_t*)(chl + c8r + k0);
            } else { cah[0] = cal[0] = cah[1] = cal[1] = 0; }
            if (k8 + 1 < Hh) {
                cah[2] = *(const uint32_t*)(chh + c0r + k8);
                cal[2] = *(const uint32_t*)(chl + c0r + k8);
                cah[3] = *(const uint32_t*)(chh + c8r + k8);
                cal[3] = *(const uint32_t*)(chl + c8r + k8);
            } else if (k8 < Hh) {
                uint32_t vh = (uint32_t)*(const uint16_t*)(chh + c0r + k8);
                uint32_t vl = (uint32_t)*(const uint16_t*)(chl + c0r + k8);
                cah[2] = vh; cal[2] = vl;
                vh = (uint32_t)*(const uint16_t*)(chh + c8r + k8);
                vl = (uint32_t)*(const uint16_t*)(chl + c8r + k8);
                cah[3] = vh; cal[3] = vl;
            } else { cah[2] = cal[2] = cah[3] = cal[3] = 0; }
        }

        // ---- stage 1: H = Dw^T @ XW1, +bias, relu -> sH[h][p]
        #pragma unroll
        for (int ti = 0; ti < 11; ++ti) {
            const int tw = w + ti * 8;
            if (tw >= 86) break;
            const int hrow = tw * 8 + gid;
            const uint32_t xh0 = *(const uint32_t*)(sXh + hrow * XH_STR + qid * 2);
            const uint32_t xh1 = *(const uint32_t*)(sXh + hrow * XH_STR + qid * 2 + 8);
            const uint32_t xl0 = *(const uint32_t*)(sXl + hrow * XH_STR + qid * 2);
            const uint32_t xl1 = *(const uint32_t*)(sXl + hrow * XH_STR + qid * 2 + 8);
            float cf[4] = {0.f, 0.f, 0.f, 0.f};
            mma_bf16(cf, dah[0], dah[1], dah[2], dah[3], xh0, xh1);
            mma_bf16(cf, dah[0], dah[1], dah[2], dah[3], xl0, xl1);
            mma_bf16(cf, dal[0], dal[1], dal[2], dal[3], xh0, xh1);
            const int ha = tw * 8 + qid * 2, hb = ha + 1;
            const float ba = sb[ha], bb = sb[hb];
            const float v00 = fmaxf(cf[0] + ba, 0.f);
            const float v01 = fmaxf(cf[1] + bb, 0.f);
            const float v10 = fmaxf(cf[2] + ba, 0.f);
            const float v11 = fmaxf(cf[3] + bb, 0.f);
            bf16 hi, lo;
            split2(v00, hi, lo); sHh[ha * XH_STR + gid]     = hi; sHl[ha * XH_STR + gid]     = lo;
            split2(v01, hi, lo); sHh[hb * XH_STR + gid]     = hi; sHl[hb * XH_STR + gid]     = lo;
            split2(v10, hi, lo); sHh[ha * XH_STR + gid + 8] = hi; sHl[ha * XH_STR + gid + 8] = lo;
            split2(v11, hi, lo); sHh[hb * XH_STR + gid + 8] = hi; sHl[hb * XH_STR + gid + 8] = lo;
        }
        __syncwarp();

        // ---- stage 2: G += Cw_chunk @ H_chunk
        #pragma unroll
        for (int ti = 0; ti < 11; ++ti) {
            const int tw = w + ti * 8;
            if (tw >= 86) break;
            const int hrow = tw * 8 + gid;
            const uint32_t hh0 = *(const uint32_t*)(sHh + hrow * XH_STR + qid * 2);
            const uint32_t hh1 = *(const uint32_t*)(sHh + hrow * XH_STR + qid * 2 + 8);
            const uint32_t hl0 = *(const uint32_t*)(sHl + hrow * XH_STR + qid * 2);
            const uint32_t hl1 = *(const uint32_t*)(sHl + hrow * XH_STR + qid * 2 + 8);
            mma_bf16(acc[ti], cah[0], cah[1], cah[2], cah[3], hh0, hh1);
            mma_bf16(acc[ti], cah[0], cah[1], cah[2], cah[3], hl0, hl1);
            mma_bf16(acc[ti], cal[0], cal[1], cal[2], cal[3], hh0, hh1);
        }
        __syncwarp();
    }

    // ---- store G (bf16 hi/lo)
    const long long g0 = ((long long)(b * Mt + gid) * Ne + n) * Hh;
    const long long g8 = g0 + 8 * mstep;
    #pragma unroll
    for (int ti = 0; ti < 11; ++ti) {
        const int tw = w + ti * 8;
        if (tw >= 86) break;
        const int ha = tw * 8 + qid * 2, hb = ha + 1;
        if (ha < Hh) {
            st_split(gh, gl, g0 + ha, acc[ti][0]);
            st_split(gh, gl, g8 + ha, acc[ti][2]);
        }
        if (hb < Hh) {
            st_split(gh, gl, g0 + hb, acc[ti][1]);
            st_split(gh, gl, g8 + hb, acc[ti][3]);
        }
    }
}

// ---------------- ypart_reduce ----------------
__global__ void ypart_reduce(const float* __restrict__ part, const float* __restrict__ b2s,
                             float* __restrict__ Y)
{
    const int i4 = blockIdx.x * blockDim.x + threadIdx.x;
    const int idx = i4 * 4;
    const int col = idx & (OUTD - 1);
    float4 s = *(const float4*)(b2s + col);
    #pragma unroll
    for (int z = 0; z < YSPLIT; ++z) {
        float4 p = *(const float4*)(part + z * (Rows * OUTD) + idx);
        s.x += p.x; s.y += p.y; s.z += p.z; s.w += p.w;
    }
    *(float4*)(Y + idx) = s;
}

// ---------------- output GEMM ----------------
__global__ __launch_bounds__(128) void out_partial(const float* __restrict__ Y,
                                                   const float* __restrict__ Wout,
                                                   float* __restrict__ part)
{
    constexpr int KC = (Mt * Dd) / OSPLIT;
    __shared__ float ys[Bb][KC];
    const int tid = threadIdx.x;
    const int col = tid * 4;
    const int k0  = blockIdx.y * KC;

    for (int idx = tid; idx < Bb * KC; idx += 128) {
        const int bi = idx / KC, kk = idx - bi * KC;
        ys[bi][kk] = Y[bi * (Mt * Dd) + k0 + kk];
    }
    __syncthreads();

    float4 acc[Bb];
    #pragma unroll
    for (int bi = 0; bi < Bb; ++bi) acc[bi] = make_float4(0.f,0.f,0.f,0.f);

    for (int kk = 0; kk < KC; ++kk) {
        const float4 w = *(const float4*)(Wout + (k0 + kk) * OUTD + col);
        #pragma unroll
        for (int bi = 0; bi < Bb; ++bi) {
            const float yv = ys[bi][kk];
            acc[bi].x = fmaf(yv, w.x, acc[bi].x);
            acc[bi].y = fmaf(yv, w.y, acc[bi].y);
            acc[bi].z = fmaf(yv, w.z, acc[bi].z);
            acc[bi].w = fmaf(yv, w.w, acc[bi].w);
        }
    }
    #pragma unroll
    for (int bi = 0; bi < Bb; ++bi)
        *(float4*)(part + (blockIdx.y * Bb + bi) * OUTD + col) = acc[bi];
}

__global__ void out_reduce(const float* __restrict__ part, const float* __restrict__ bout,
                           float* __restrict__ out)
{
    const int i4 = blockIdx.x * blockDim.x + threadIdx.x;
    const int idx = i4 * 4;
    const int col = idx & (OUTD - 1);
    const int bi  = idx >> 9;
    float4 s = *(const float4*)(bout + col);
    #pragma unroll
    for (int z = 0; z < OSPLIT; ++z) {
        float4 p = *(const float4*)(part + (z * Bb + bi) * OUTD + col);
        s.x += p.x; s.y += p.y; s.z += p.z; s.w += p.w;
    }
    *(float4*)(out + idx) = s;
}

// ---------------- launch ----------------
extern "C" void kernel_launch(void* const* d_in, const int* in_sizes, int n_in,
                              void* d_out, int out_size)
{
    const float* x    = (const float*)d_in[0];
    const float* phi  = (const float*)d_in[1];
    const float* W1   = (const float*)d_in[2];
    const float* b1   = (const float*)d_in[3];
    const float* W2   = (const float*)d_in[4];
    const float* b2   = (const float*)d_in[5];
    const float* Wout = (const float*)d_in[6];
    const float* bout = (const float*)d_in[7];
    float* out = (float*)d_out;

    float *p_logits, *p_XW1, *p_Ypart, *p_Y, *p_b2sum, *p_opart;
    bf16 *p_xh, *p_xl, *p_gh, *p_gl, *p_chh, *p_chl;
    cudaGetSymbolAddress((void**)&p_logits, g_logits);
    cudaGetSymbolAddress((void**)&p_XW1,    g_XW1);
    cudaGetSymbolAddress((void**)&p_Ypart,  g_Ypart);
    cudaGetSymbolAddress((void**)&p_Y,      g_Y);
    cudaGetSymbolAddress((void**)&p_b2sum,  g_b2sum);
    cudaGetSymbolAddress((void**)&p_opart,  g_opart);
    cudaGetSymbolAddress((void**)&p_xh,   g_xh);
    cudaGetSymbolAddress((void**)&p_xl,   g_xl);
    cudaGetSymbolAddress((void**)&p_gh,   g_gh);
    cudaGetSymbolAddress((void**)&p_gl,   g_gl);
    cudaGetSymbolAddress((void**)&p_chh,  g_chh);
    cudaGetSymbolAddress((void**)&p_chl,  g_chl);

    cudaFuncSetAttribute(mma_gemm<0>, cudaFuncAttributeMaxDynamicSharedMemorySize, MG_SMEM);
    cudaFuncSetAttribute(mma_gemm<1>, cudaFuncAttributeMaxDynamicSharedMemorySize, MG_SMEM);
    cudaFuncSetAttribute(fused_G_tc,  cudaFuncAttributeMaxDynamicSharedMemorySize, FG_SMEM);

    prep_k<<<CVT_BLOCKS + 2, 256>>>(x, p_xh, p_xl, b2, p_b2sum);

    const dim3 gBig((NHt + 63)/64, Rows/128, 1);             // 171 x 2
    mma_gemm<0><<<gBig, 256, MG_SMEM>>>(p_xh, p_xl, phi, p_logits, NHt, Dd, 1);
    mma_gemm<1><<<gBig, 256, MG_SMEM>>>(p_xh, p_xl, W1,  p_XW1,    NHt, Dd, 1);

    softmax_np<<<Rows, 256>>>(p_logits, p_chh, p_chl);

    fused_G_tc<<<Bb*Ne, 256, FG_SMEM>>>(p_XW1, p_logits, p_chh, p_chl, b1, p_gh, p_gl);

    const dim3 gY(OUTD/64, Rows/128, YSPLIT);                // 8 x 2 x 16
    mma_gemm<0><<<gY, 256, MG_SMEM>>>(p_gh, p_gl, W2, p_Ypart, OUTD, NHt, YSPLIT);
    ypart_reduce<<<(Rows*OUTD/4)/256, 256>>>(p_Ypart, p_b2sum, p_Y);

    const dim3 gO(1, OSPLIT, 1);
    out_partial<<<gO, 128>>>(p_Y, Wout, p_opart);
    out_reduce <<<(Bb*OUTD/4)/256, 256>>>(p_opart, bout, out);
}